// round 9
// baseline (speedup 1.0000x reference)
#include <cuda_runtime.h>
#include <cuda_bf16.h>
#include <cstdint>

#define N_NODES 100000
#define E_EDGES 500000
#define NTILES  ((E_EDGES + 127) / 128)   // 3907
#define GRID_E  148

// ---------------------------------------------------------------------------
// Device scratch
// ---------------------------------------------------------------------------
__device__ float g_UV[(size_t)N_NODES * 512];   // per node: U[0:256], V[256:512]
__device__ uint4 g_nBhi4[16384];                // node B: 8 chunks x 128x128 bf16
__device__ uint4 g_nBlo4[16384];
__device__ uint4 g_eBhi4[4096];                 // edge B (W2): 2 chunks x 128x128 bf16
__device__ uint4 g_eBlo4[4096];
__device__ int   g_idx64;

#define CHUNK_U4 2048   // 128*128 bf16 = 32768 B = 2048 uint4

// ---------------- node kernel smem layout (R8, unchanged) ----------------
#define OFF_AHI  1024
#define OFF_ALO  (1024 + 67584)
#define OFF_BHI  (1024 + 2 * 67584)
#define OFF_BLO  (1024 + 2 * 67584 + 34816)
#define SM_BYTES (1024 + 2 * 67584 + 2 * 34816)   // 205824
#define PITCH_A  528
#define PITCH_B  272
#define STG_PITCH 132

// ---------------- edge kernel smem layout (persistent) -------------------
#define PA 144                       // A row: 64 bf16 (128B) + 16 pad
#define PB 528                       // B row: 256 bf16 (512B) + 16 pad
#define A_HALF (128 * PA)            // 18432
#define EA0H 0
#define EA0L (EA0H + A_HALF)
#define EA1H (EA0L + A_HALF)
#define EA1L (EA1H + A_HALF)
#define EBH  (EA1L + A_HALF)         // 73728
#define EBL  (EBH + 128 * PB)        // 141312
#define SM_E (EBL + 128 * PB)        // 208896

__device__ __forceinline__ uint32_t smem_u32(const void* p) {
    uint32_t a;
    asm("{ .reg .u64 t; cvta.to.shared.u64 t, %1; cvt.u32.u64 %0, t; }" : "=r"(a) : "l"(p));
    return a;
}

__device__ __forceinline__ void ldsm_x4(uint32_t* r, uint32_t addr) {
    asm volatile("ldmatrix.sync.aligned.m8n8.x4.shared.b16 {%0,%1,%2,%3}, [%4];"
                 : "=r"(r[0]), "=r"(r[1]), "=r"(r[2]), "=r"(r[3]) : "r"(addr));
}

__device__ __forceinline__ void mma16816(float* d, const uint32_t* a, const uint32_t* b) {
    asm volatile(
        "mma.sync.aligned.m16n8k16.row.col.f32.bf16.bf16.f32 "
        "{%0,%1,%2,%3},{%4,%5,%6,%7},{%8,%9},{%0,%1,%2,%3};"
        : "+f"(d[0]), "+f"(d[1]), "+f"(d[2]), "+f"(d[3])
        : "r"(a[0]), "r"(a[1]), "r"(a[2]), "r"(a[3]), "r"(b[0]), "r"(b[1]));
}

__device__ __forceinline__ void cpasync16(uint32_t saddr, const void* g) {
    asm volatile("cp.async.ca.shared.global [%0], [%1], 16;" :: "r"(saddr), "l"(g));
}
__device__ __forceinline__ void cp_commit() { asm volatile("cp.async.commit_group;"); }
__device__ __forceinline__ void cp_wait0()  { asm volatile("cp.async.wait_group 0;" ::: "memory"); }

__device__ __forceinline__ void split2(float a, float b, uint32_t& hi, uint32_t& lo) {
    __nv_bfloat16 ah = __float2bfloat16_rn(a);
    __nv_bfloat16 bh = __float2bfloat16_rn(b);
    __nv_bfloat16 al = __float2bfloat16_rn(a - __bfloat162float(ah));
    __nv_bfloat16 bl = __float2bfloat16_rn(b - __bfloat162float(bh));
    hi = (uint32_t)__bfloat16_as_ushort(ah) | ((uint32_t)__bfloat16_as_ushort(bh) << 16);
    lo = (uint32_t)__bfloat16_as_ushort(al) | ((uint32_t)__bfloat16_as_ushort(bl) << 16);
}

// ---------------------------------------------------------------------------
// detect edge_index dtype (int64 vs int32)
// ---------------------------------------------------------------------------
__global__ void detect_kernel(const unsigned* __restrict__ ei) {
    if (threadIdx.x == 0 && blockIdx.x == 0) {
        int ok = 1;
        #pragma unroll 1
        for (int i = 0; i < 256; i++)
            if (ei[2 * i + 1] != 0u) { ok = 0; break; }
        g_idx64 = ok;
    }
}

// ---------------------------------------------------------------------------
// prep: split weights into bf16 hi/lo chunk blobs [chunk][row][k] (128x128)
// ---------------------------------------------------------------------------
__global__ void prep_kernel(const float* __restrict__ W1, const float* __restrict__ W2) {
    int idx = blockIdx.x * blockDim.x + threadIdx.x;
    float v;
    uint32_t off;
    __nv_bfloat16 *dh, *dl;
    if (idx < 131072) {
        int j = idx >> 8, k = idx & 255;
        v = (j < 256) ? W1[j * 512 + k] : W1[(j - 256) * 512 + 256 + k];
        int nc = j >> 7, row = j & 127, kc = k >> 7, kp = k & 127;
        off = (uint32_t)(kc * 4 + nc) * 16384u + row * 128 + kp;
        dh = (__nv_bfloat16*)g_nBhi4; dl = (__nv_bfloat16*)g_nBlo4;
    } else {
        int e = idx - 131072;
        if (e >= 32768) return;
        int n = e >> 8, k = e & 255;
        v = W2[n * 256 + k];
        int kc = k >> 7, kp = k & 127;
        off = (uint32_t)kc * 16384u + n * 128 + kp;
        dh = (__nv_bfloat16*)g_eBhi4; dl = (__nv_bfloat16*)g_eBlo4;
    }
    __nv_bfloat16 h = __float2bfloat16_rn(v);
    dh[off] = h;
    dl[off] = __float2bfloat16_rn(v - __bfloat162float(h));
}

// ---------------------------------------------------------------------------
// node kernel helpers (R8, unchanged)
// ---------------------------------------------------------------------------
__device__ __forceinline__ void load_B_async_n(uint32_t smB_hi, uint32_t smB_lo,
                                               const uint4* srcH, const uint4* srcL, int tid) {
    #pragma unroll
    for (int i = 0; i < 8; i++) {
        int idx = i * 256 + tid;
        int row = idx >> 4, c = idx & 15;
        uint32_t d = row * PITCH_B + c * 16;
        cpasync16(smB_hi + d, srcH + idx);
        cpasync16(smB_lo + d, srcL + idx);
    }
    cp_commit();
}

__device__ __forceinline__ void mma_chunk_n(float d[4][4][4],
                                            uint32_t aHiBase, uint32_t aLoBase,
                                            uint32_t bHiBase, uint32_t bLoBase) {
    #pragma unroll 1
    for (int ks = 0; ks < 8; ks++) {
        uint32_t Ah[4][4], Al[4][4], Bh[2][4], Bl[2][4];
        #pragma unroll
        for (int f = 0; f < 4; f++) {
            ldsm_x4(Ah[f], aHiBase + f * (16 * PITCH_A) + ks * 32);
            ldsm_x4(Al[f], aLoBase + f * (16 * PITCH_A) + ks * 32);
        }
        #pragma unroll
        for (int gp = 0; gp < 2; gp++) {
            ldsm_x4(Bh[gp], bHiBase + gp * (16 * PITCH_B) + ks * 32);
            ldsm_x4(Bl[gp], bLoBase + gp * (16 * PITCH_B) + ks * 32);
        }
        #pragma unroll
        for (int f = 0; f < 4; f++)
            #pragma unroll
            for (int g = 0; g < 4; g++) {
                const uint32_t* bh = &Bh[g >> 1][(g & 1) * 2];
                const uint32_t* bl = &Bl[g >> 1][(g & 1) * 2];
                mma16816(d[f][g], Ah[f], bh);
                mma16816(d[f][g], Ah[f], bl);
                mma16816(d[f][g], Al[f], bh);
            }
    }
}

// ---------------------------------------------------------------------------
// node kernel (R8, unchanged): UV[128,512] = Z @ B^T
// ---------------------------------------------------------------------------
__global__ void __launch_bounds__(256, 1) node_mma(const float* __restrict__ Z) {
    extern __shared__ char sm[];
    const uint32_t smb = smem_u32(sm);
    const int tid = threadIdx.x, lane = tid & 31, wid = tid >> 5;
    const int wm = wid & 1, wn = wid >> 1;
    const int mbase = blockIdx.x * 128;

    load_B_async_n(smb + OFF_BHI, smb + OFF_BLO, g_nBhi4, g_nBlo4, tid);

    {
        const int lrow = tid >> 3;
        const int lk = (tid & 7) * 4;
        #pragma unroll 1
        for (int s = 0; s < 4; s++) {
            int row = s * 32 + lrow;
            int gr = min(mbase + row, N_NODES - 1);
            const float* zr = Z + (size_t)gr * 256;
            char* ah = sm + OFF_AHI + row * PITCH_A;
            char* al = sm + OFF_ALO + row * PITCH_A;
            #pragma unroll
            for (int i = 0; i < 8; i++) {
                int k = lk + i * 32;
                float4 z4 = *(const float4*)(zr + k);
                uint32_t h0, l0, h1, l1;
                split2(z4.x, z4.y, h0, l0);
                split2(z4.z, z4.w, h1, l1);
                *(uint2*)(ah + k * 2) = make_uint2(h0, h1);
                *(uint2*)(al + k * 2) = make_uint2(l0, l1);
            }
        }
    }

    uint32_t aHi, aLo, bHi, bLo;
    {
        int row = wm * 64 + (lane & 7) + ((lane >> 3) & 1) * 8;
        aHi = smb + OFF_AHI + row * PITCH_A + ((lane >> 4) & 1) * 16;
        aLo = smb + OFF_ALO + row * PITCH_A + ((lane >> 4) & 1) * 16;
        int n = wn * 32 + (lane & 7) + ((lane >> 4) & 1) * 8;
        bHi = smb + OFF_BHI + n * PITCH_B + ((lane >> 3) & 1) * 16;
        bLo = smb + OFF_BLO + n * PITCH_B + ((lane >> 3) & 1) * 16;
    }
    float* stg = (float*)(sm + OFF_BHI);

    #pragma unroll 1
    for (int nc = 0; nc < 4; nc++) {
        float d[4][4][4];
        #pragma unroll
        for (int f = 0; f < 4; f++)
            #pragma unroll
            for (int g = 0; g < 4; g++)
                #pragma unroll
                for (int c = 0; c < 4; c++) d[f][g][c] = 0.f;

        #pragma unroll 1
        for (int kc = 0; kc < 2; kc++) {
            cp_wait0();
            __syncthreads();
            mma_chunk_n(d, aHi + kc * 256, aLo + kc * 256, bHi, bLo);
            __syncthreads();
            if (kc == 0)
                load_B_async_n(smb + OFF_BHI, smb + OFF_BLO,
                               g_nBhi4 + (1 * 4 + nc) * CHUNK_U4,
                               g_nBlo4 + (1 * 4 + nc) * CHUNK_U4, tid);
        }

        #pragma unroll
        for (int g = 0; g < 4; g++) {
            int col = wn * 32 + g * 8 + (lane & 3) * 2;
            #pragma unroll
            for (int f = 0; f < 4; f++) {
                int r0 = wm * 64 + f * 16 + (lane >> 2);
                *(float2*)(stg + r0 * STG_PITCH + col) = make_float2(d[f][g][0], d[f][g][1]);
                *(float2*)(stg + (r0 + 8) * STG_PITCH + col) = make_float2(d[f][g][2], d[f][g][3]);
            }
        }
        __syncthreads();
        {
            const int c = (tid & 31) * 4;
            #pragma unroll
            for (int i = 0; i < 16; i++) {
                int idx = i * 256 + tid;
                int row = idx >> 5;
                int gr = mbase + row;
                if (gr < N_NODES) {
                    float4 v = *(const float4*)(stg + row * STG_PITCH + c);
                    *(float4*)(g_UV + (size_t)gr * 512 + nc * 128 + c) = v;
                }
            }
        }
        __syncthreads();
        if (nc < 3)
            load_B_async_n(smb + OFF_BHI, smb + OFF_BLO,
                           g_nBhi4 + (nc + 1) * CHUNK_U4,
                           g_nBlo4 + (nc + 1) * CHUNK_U4, tid);
    }
}

// ---------------------------------------------------------------------------
// edge kernel: persistent producer/consumer pipeline
//   384 thr: warps 0-7 = consumers (mma 64x32 tiles), warps 8-11 = producers
//   A staged in 64-k quarters, ping-pong; W2 resident full-K in smem
// ---------------------------------------------------------------------------
__global__ void __launch_bounds__(384, 1) edge_mma(const void* __restrict__ EI,
                                                   const float* __restrict__ b1,
                                                   const float* __restrict__ b2,
                                                   float* __restrict__ out) {
    extern __shared__ char sm[];
    const uint32_t smb = smem_u32(sm);
    const int tid = threadIdx.x, lane = tid & 31, wid = tid >> 5;
    const int bid = blockIdx.x;
    const int nt = (NTILES - bid + GRID_E - 1) / GRID_E;
    const int nsteps = nt * 4;

    // ---- prologue ----
    if (wid < 8) {
        // consumers: load resident W2 (full K) into smem via cp.async
        int ctid = tid;  // 0..255
        #pragma unroll
        for (int i = 0; i < 16; i++) {
            int idx = i * 256 + ctid;             // 0..4095 over hi; same for lo
            int kc = idx >> 11;
            int r = (idx >> 4) & 127;
            int c = idx & 15;
            uint32_t dst = r * PB + kc * 256 + c * 16;
            cpasync16(smb + EBH + dst, g_eBhi4 + kc * CHUNK_U4 + (idx & 2047));
            cpasync16(smb + EBL + dst, g_eBlo4 + kc * CHUNK_U4 + (idx & 2047));
        }
        cp_commit();
        cp_wait0();
    } else {
        // producers: gather step 0 into buf0
        const int r = tid - 256;                  // 0..127
        long long e = (long long)bid * 128 + r;
        if (e >= E_EDGES) e = E_EDGES - 1;
        int si, di;
        if (g_idx64) {
            const long long* p = (const long long*)EI;
            si = (int)p[e]; di = (int)p[e + E_EDGES];
        } else {
            const int* p = (const int*)EI;
            si = p[e]; di = p[e + E_EDGES];
        }
        si = min(max(si, 0), N_NODES - 1);
        di = min(max(di, 0), N_NODES - 1);
        const float* U = g_UV + (size_t)si * 512;
        const float* V = g_UV + (size_t)di * 512 + 256;
        char* ah = sm + EA0H + r * PA;
        char* al = sm + EA0L + r * PA;
        #pragma unroll
        for (int i = 0; i < 16; i++) {
            float4 u4 = *(const float4*)(U + i * 4);
            float4 v4 = *(const float4*)(V + i * 4);
            float4 c4 = *(const float4*)(b1 + i * 4);
            float h0 = fmaxf(u4.x + v4.x + c4.x, 0.f);
            float h1 = fmaxf(u4.y + v4.y + c4.y, 0.f);
            float h2 = fmaxf(u4.z + v4.z + c4.z, 0.f);
            float h3 = fmaxf(u4.w + v4.w + c4.w, 0.f);
            uint32_t H0, L0, H1, L1;
            split2(h0, h1, H0, L0);
            split2(h2, h3, H1, L1);
            *(uint2*)(ah + i * 8) = make_uint2(H0, H1);
            *(uint2*)(al + i * 8) = make_uint2(L0, L1);
        }
    }
    __syncthreads();

    // ---- consumer-side constants ----
    const int wm = wid & 1, wn = wid >> 1;        // valid for wid<8
    uint32_t aOff = 0, bHi = 0, bLo = 0;
    float2 b2v[4];
    if (wid < 8) {
        int row = wm * 64 + (lane & 7) + ((lane >> 3) & 1) * 8;
        aOff = row * PA + ((lane >> 4) & 1) * 16;
        int n = wn * 32 + (lane & 7) + ((lane >> 4) & 1) * 8;
        bHi = smb + EBH + n * PB + ((lane >> 3) & 1) * 16;
        bLo = smb + EBL + n * PB + ((lane >> 3) & 1) * 16;
        #pragma unroll
        for (int g = 0; g < 4; g++)
            b2v[g] = *(const float2*)(b2 + wn * 32 + g * 8 + (lane & 3) * 2);
    }

    float d[4][4][4];
    #pragma unroll
    for (int f = 0; f < 4; f++)
        #pragma unroll
        for (int g = 0; g < 4; g++)
            #pragma unroll
            for (int c = 0; c < 4; c++) d[f][g][c] = 0.f;

    // ---- steady-state pipeline ----
    #pragma unroll 1
    for (int s = 0; s < nsteps; s++) {
        if (wid >= 8) {
            // producers: gather step s+1 into buf[(s+1)&1]
            int ss = s + 1;
            if (ss < nsteps) {
                int j = ss >> 2, q = ss & 3;
                int t = bid + j * GRID_E;
                const int r = tid - 256;
                long long e = (long long)t * 128 + r;
                if (e >= E_EDGES) e = E_EDGES - 1;
                int si, di;
                if (g_idx64) {
                    const long long* p = (const long long*)EI;
                    si = (int)p[e]; di = (int)p[e + E_EDGES];
                } else {
                    const int* p = (const int*)EI;
                    si = p[e]; di = p[e + E_EDGES];
                }
                si = min(max(si, 0), N_NODES - 1);
                di = min(max(di, 0), N_NODES - 1);
                const float* U = g_UV + (size_t)si * 512 + q * 64;
                const float* V = g_UV + (size_t)di * 512 + 256 + q * 64;
                const float* Bb = b1 + q * 64;
                char* ah = sm + ((ss & 1) ? EA1H : EA0H) + r * PA;
                char* al = sm + ((ss & 1) ? EA1L : EA0L) + r * PA;
                #pragma unroll
                for (int i = 0; i < 16; i++) {
                    float4 u4 = *(const float4*)(U + i * 4);
                    float4 v4 = *(const float4*)(V + i * 4);
                    float4 c4 = *(const float4*)(Bb + i * 4);
                    float h0 = fmaxf(u4.x + v4.x + c4.x, 0.f);
                    float h1 = fmaxf(u4.y + v4.y + c4.y, 0.f);
                    float h2 = fmaxf(u4.z + v4.z + c4.z, 0.f);
                    float h3 = fmaxf(u4.w + v4.w + c4.w, 0.f);
                    uint32_t H0, L0, H1, L1;
                    split2(h0, h1, H0, L0);
                    split2(h2, h3, H1, L1);
                    *(uint2*)(ah + i * 8) = make_uint2(H0, H1);
                    *(uint2*)(al + i * 8) = make_uint2(L0, L1);
                }
            }
        } else {
            // consumers: mma quarter s from buf[s&1]
            const int q = s & 3;
            uint32_t aHi = smb + ((s & 1) ? EA1H : EA0H) + aOff;
            uint32_t aLo = smb + ((s & 1) ? EA1L : EA0L) + aOff;
            #pragma unroll
            for (int ks = 0; ks < 4; ks++) {
                uint32_t Ah[4][4], Al[4][4], Bh[2][4], Bl[2][4];
                #pragma unroll
                for (int f = 0; f < 4; f++) {
                    ldsm_x4(Ah[f], aHi + f * (16 * PA) + ks * 32);
                    ldsm_x4(Al[f], aLo + f * (16 * PA) + ks * 32);
                }
                #pragma unroll
                for (int gp = 0; gp < 2; gp++) {
                    ldsm_x4(Bh[gp], bHi + gp * (16 * PB) + (q * 4 + ks) * 32);
                    ldsm_x4(Bl[gp], bLo + gp * (16 * PB) + (q * 4 + ks) * 32);
                }
                #pragma unroll
                for (int f = 0; f < 4; f++)
                    #pragma unroll
                    for (int g = 0; g < 4; g++) {
                        const uint32_t* bh = &Bh[g >> 1][(g & 1) * 2];
                        const uint32_t* bl = &Bl[g >> 1][(g & 1) * 2];
                        mma16816(d[f][g], Ah[f], bh);
                        mma16816(d[f][g], Ah[f], bl);
                        mma16816(d[f][g], Al[f], bh);
                    }
            }
            if (q == 3) {
                // epilogue for tile s>>2, then reset accumulators
                int ebase = (bid + (s >> 2) * GRID_E) * 128;
                #pragma unroll
                for (int g = 0; g < 4; g++) {
                    int col = wn * 32 + g * 8 + (lane & 3) * 2;
                    float bx = b2v[g].x, by = b2v[g].y;
                    #pragma unroll
                    for (int f = 0; f < 4; f++) {
                        int r0 = ebase + wm * 64 + f * 16 + (lane >> 2);
                        if (r0 < E_EDGES)
                            *(float2*)(out + (size_t)r0 * 128 + col) =
                                make_float2(d[f][g][0] + bx, d[f][g][1] + by);
                        int r1 = r0 + 8;
                        if (r1 < E_EDGES)
                            *(float2*)(out + (size_t)r1 * 128 + col) =
                                make_float2(d[f][g][2] + bx, d[f][g][3] + by);
                        d[f][g][0] = d[f][g][1] = d[f][g][2] = d[f][g][3] = 0.f;
                    }
                }
            }
        }
        __syncthreads();
    }
}

// ---------------------------------------------------------------------------
// launch — inputs resolved by unique element counts
// ---------------------------------------------------------------------------
extern "C" void kernel_launch(void* const* d_in, const int* in_sizes, int n_in,
                              void* d_out, int out_size) {
    const float* z = nullptr;
    const void* ei = nullptr;
    const float* W1 = nullptr;
    const float* b1 = nullptr;
    const float* W2 = nullptr;
    const float* b2 = nullptr;
    for (int i = 0; i < n_in; i++) {
        switch (in_sizes[i]) {
            case 25600000: z = (const float*)d_in[i]; break;
            case 1000000:  ei = d_in[i];              break;
            case 131072:   W1 = (const float*)d_in[i]; break;
            case 256:      b1 = (const float*)d_in[i]; break;
            case 32768:    W2 = (const float*)d_in[i]; break;
            case 128:      b2 = (const float*)d_in[i]; break;
            default: break;
        }
    }
    float* out = (float*)d_out;

    cudaFuncSetAttribute(node_mma, cudaFuncAttributeMaxDynamicSharedMemorySize, SM_BYTES);
    cudaFuncSetAttribute(edge_mma, cudaFuncAttributeMaxDynamicSharedMemorySize, SM_E);

    detect_kernel<<<1, 32>>>((const unsigned*)ei);
    prep_kernel<<<640, 256>>>(W1, W2);
    node_mma<<<(N_NODES + 127) / 128, 256, SM_BYTES>>>(z);
    edge_mma<<<GRID_E, 384, SM_E>>>(ei, b1, b2, out);
}

// round 11
// speedup vs baseline: 1.0366x; 1.0366x over previous
#include <cuda_runtime.h>
#include <cuda_bf16.h>
#include <cstdint>

#define N_NODES 100000
#define E_EDGES 500000

// ---------------------------------------------------------------------------
// Device scratch
// ---------------------------------------------------------------------------
__device__ float g_UV[(size_t)N_NODES * 512];   // per node: U[0:256], V[256:512]
__device__ uint4 g_nBhi4[16384];                // node B: 8 chunks x 128x128 bf16
__device__ uint4 g_nBlo4[16384];
__device__ uint4 g_eBhi4[4096];                 // edge B (W2): 2 chunks x 128x128 bf16
__device__ uint4 g_eBlo4[4096];
__device__ int   g_idx64;

#define CHUNK_U4 2048   // 128*128 bf16 = 32768 B = 2048 uint4 (16 uint4 per row)

// ---------------- node kernel smem layout (R8, unchanged) ----------------
#define OFF_AHI  1024
#define OFF_ALO  (1024 + 67584)
#define OFF_BHI  (1024 + 2 * 67584)
#define OFF_BLO  (1024 + 2 * 67584 + 34816)
#define SM_BYTES (1024 + 2 * 67584 + 2 * 34816)   // 205824
#define PITCH_A  528
#define PITCH_B  272
#define STG_PITCH 132

// ---------------- edge kernel smem layout (2 CTAs/SM, quarter-staged) ----
#define EP 144                        // quarter row pitch: 64 bf16 (128B) + 16
#define EA_BUF (128 * EP)             // 18432
#define EOFF_IDX 0                    // src[128], dst[128]
#define EOFF_A   1024                 // A(buf,h) = EOFF_A + buf*2*EA_BUF + h*EA_BUF
#define EOFF_BH  (1024 + 4 * EA_BUF)  // 74752
#define EOFF_BL  (EOFF_BH + EA_BUF)   // 93184
#define SM_E2    (EOFF_BL + EA_BUF)   // 111616  -> 2 CTAs/SM

__device__ __forceinline__ uint32_t smem_u32(const void* p) {
    uint32_t a;
    asm("{ .reg .u64 t; cvta.to.shared.u64 t, %1; cvt.u32.u64 %0, t; }" : "=r"(a) : "l"(p));
    return a;
}

__device__ __forceinline__ void ldsm_x4(uint32_t* r, uint32_t addr) {
    asm volatile("ldmatrix.sync.aligned.m8n8.x4.shared.b16 {%0,%1,%2,%3}, [%4];"
                 : "=r"(r[0]), "=r"(r[1]), "=r"(r[2]), "=r"(r[3]) : "r"(addr));
}

__device__ __forceinline__ void mma16816(float* d, const uint32_t* a, const uint32_t* b) {
    asm volatile(
        "mma.sync.aligned.m16n8k16.row.col.f32.bf16.bf16.f32 "
        "{%0,%1,%2,%3},{%4,%5,%6,%7},{%8,%9},{%0,%1,%2,%3};"
        : "+f"(d[0]), "+f"(d[1]), "+f"(d[2]), "+f"(d[3])
        : "r"(a[0]), "r"(a[1]), "r"(a[2]), "r"(a[3]), "r"(b[0]), "r"(b[1]));
}

__device__ __forceinline__ void cpasync16(uint32_t saddr, const void* g) {
    asm volatile("cp.async.ca.shared.global [%0], [%1], 16;" :: "r"(saddr), "l"(g));
}
__device__ __forceinline__ void cp_commit() { asm volatile("cp.async.commit_group;"); }
__device__ __forceinline__ void cp_wait0()  { asm volatile("cp.async.wait_group 0;" ::: "memory"); }

__device__ __forceinline__ void split2(float a, float b, uint32_t& hi, uint32_t& lo) {
    __nv_bfloat16 ah = __float2bfloat16_rn(a);
    __nv_bfloat16 bh = __float2bfloat16_rn(b);
    __nv_bfloat16 al = __float2bfloat16_rn(a - __bfloat162float(ah));
    __nv_bfloat16 bl = __float2bfloat16_rn(b - __bfloat162float(bh));
    hi = (uint32_t)__bfloat16_as_ushort(ah) | ((uint32_t)__bfloat16_as_ushort(bh) << 16);
    lo = (uint32_t)__bfloat16_as_ushort(al) | ((uint32_t)__bfloat16_as_ushort(bl) << 16);
}

// ---------------------------------------------------------------------------
// detect edge_index dtype (int64 vs int32)
// ---------------------------------------------------------------------------
__global__ void detect_kernel(const unsigned* __restrict__ ei) {
    if (threadIdx.x == 0 && blockIdx.x == 0) {
        int ok = 1;
        #pragma unroll 1
        for (int i = 0; i < 256; i++)
            if (ei[2 * i + 1] != 0u) { ok = 0; break; }
        g_idx64 = ok;
    }
}

// ---------------------------------------------------------------------------
// prep: split weights into bf16 hi/lo chunk blobs [chunk][row][k] (128x128)
// ---------------------------------------------------------------------------
__global__ void prep_kernel(const float* __restrict__ W1, const float* __restrict__ W2) {
    int idx = blockIdx.x * blockDim.x + threadIdx.x;
    float v;
    uint32_t off;
    __nv_bfloat16 *dh, *dl;
    if (idx < 131072) {
        int j = idx >> 8, k = idx & 255;
        v = (j < 256) ? W1[j * 512 + k] : W1[(j - 256) * 512 + 256 + k];
        int nc = j >> 7, row = j & 127, kc = k >> 7, kp = k & 127;
        off = (uint32_t)(kc * 4 + nc) * 16384u + row * 128 + kp;
        dh = (__nv_bfloat16*)g_nBhi4; dl = (__nv_bfloat16*)g_nBlo4;
    } else {
        int e = idx - 131072;
        if (e >= 32768) return;
        int n = e >> 8, k = e & 255;
        v = W2[n * 256 + k];
        int kc = k >> 7, kp = k & 127;
        off = (uint32_t)kc * 16384u + n * 128 + kp;
        dh = (__nv_bfloat16*)g_eBhi4; dl = (__nv_bfloat16*)g_eBlo4;
    }
    __nv_bfloat16 h = __float2bfloat16_rn(v);
    dh[off] = h;
    dl[off] = __float2bfloat16_rn(v - __bfloat162float(h));
}

// ---------------------------------------------------------------------------
// node kernel helpers (R8, unchanged)
// ---------------------------------------------------------------------------
__device__ __forceinline__ void load_B_async_n(uint32_t smB_hi, uint32_t smB_lo,
                                               const uint4* srcH, const uint4* srcL, int tid) {
    #pragma unroll
    for (int i = 0; i < 8; i++) {
        int idx = i * 256 + tid;
        int row = idx >> 4, c = idx & 15;
        uint32_t d = row * PITCH_B + c * 16;
        cpasync16(smB_hi + d, srcH + idx);
        cpasync16(smB_lo + d, srcL + idx);
    }
    cp_commit();
}

__device__ __forceinline__ void mma_chunk_n(float d[4][4][4],
                                            uint32_t aHiBase, uint32_t aLoBase,
                                            uint32_t bHiBase, uint32_t bLoBase) {
    #pragma unroll 1
    for (int ks = 0; ks < 8; ks++) {
        uint32_t Ah[4][4], Al[4][4], Bh[2][4], Bl[2][4];
        #pragma unroll
        for (int f = 0; f < 4; f++) {
            ldsm_x4(Ah[f], aHiBase + f * (16 * PITCH_A) + ks * 32);
            ldsm_x4(Al[f], aLoBase + f * (16 * PITCH_A) + ks * 32);
        }
        #pragma unroll
        for (int gp = 0; gp < 2; gp++) {
            ldsm_x4(Bh[gp], bHiBase + gp * (16 * PITCH_B) + ks * 32);
            ldsm_x4(Bl[gp], bLoBase + gp * (16 * PITCH_B) + ks * 32);
        }
        #pragma unroll
        for (int f = 0; f < 4; f++)
            #pragma unroll
            for (int g = 0; g < 4; g++) {
                const uint32_t* bh = &Bh[g >> 1][(g & 1) * 2];
                const uint32_t* bl = &Bl[g >> 1][(g & 1) * 2];
                mma16816(d[f][g], Ah[f], bh);
                mma16816(d[f][g], Ah[f], bl);
                mma16816(d[f][g], Al[f], bh);
            }
    }
}

// ---------------------------------------------------------------------------
// node kernel (R8, unchanged): UV[128,512] = Z @ B^T
// ---------------------------------------------------------------------------
__global__ void __launch_bounds__(256, 1) node_mma(const float* __restrict__ Z) {
    extern __shared__ char sm[];
    const uint32_t smb = smem_u32(sm);
    const int tid = threadIdx.x, lane = tid & 31, wid = tid >> 5;
    const int wm = wid & 1, wn = wid >> 1;
    const int mbase = blockIdx.x * 128;

    load_B_async_n(smb + OFF_BHI, smb + OFF_BLO, g_nBhi4, g_nBlo4, tid);

    {
        const int lrow = tid >> 3;
        const int lk = (tid & 7) * 4;
        #pragma unroll 1
        for (int s = 0; s < 4; s++) {
            int row = s * 32 + lrow;
            int gr = min(mbase + row, N_NODES - 1);
            const float* zr = Z + (size_t)gr * 256;
            char* ah = sm + OFF_AHI + row * PITCH_A;
            char* al = sm + OFF_ALO + row * PITCH_A;
            #pragma unroll
            for (int i = 0; i < 8; i++) {
                int k = lk + i * 32;
                float4 z4 = *(const float4*)(zr + k);
                uint32_t h0, l0, h1, l1;
                split2(z4.x, z4.y, h0, l0);
                split2(z4.z, z4.w, h1, l1);
                *(uint2*)(ah + k * 2) = make_uint2(h0, h1);
                *(uint2*)(al + k * 2) = make_uint2(l0, l1);
            }
        }
    }

    uint32_t aHi, aLo, bHi, bLo;
    {
        int row = wm * 64 + (lane & 7) + ((lane >> 3) & 1) * 8;
        aHi = smb + OFF_AHI + row * PITCH_A + ((lane >> 4) & 1) * 16;
        aLo = smb + OFF_ALO + row * PITCH_A + ((lane >> 4) & 1) * 16;
        int n = wn * 32 + (lane & 7) + ((lane >> 4) & 1) * 8;
        bHi = smb + OFF_BHI + n * PITCH_B + ((lane >> 3) & 1) * 16;
        bLo = smb + OFF_BLO + n * PITCH_B + ((lane >> 3) & 1) * 16;
    }
    float* stg = (float*)(sm + OFF_BHI);

    #pragma unroll 1
    for (int nc = 0; nc < 4; nc++) {
        float d[4][4][4];
        #pragma unroll
        for (int f = 0; f < 4; f++)
            #pragma unroll
            for (int g = 0; g < 4; g++)
                #pragma unroll
                for (int c = 0; c < 4; c++) d[f][g][c] = 0.f;

        #pragma unroll 1
        for (int kc = 0; kc < 2; kc++) {
            cp_wait0();
            __syncthreads();
            mma_chunk_n(d, aHi + kc * 256, aLo + kc * 256, bHi, bLo);
            __syncthreads();
            if (kc == 0)
                load_B_async_n(smb + OFF_BHI, smb + OFF_BLO,
                               g_nBhi4 + (1 * 4 + nc) * CHUNK_U4,
                               g_nBlo4 + (1 * 4 + nc) * CHUNK_U4, tid);
        }

        #pragma unroll
        for (int g = 0; g < 4; g++) {
            int col = wn * 32 + g * 8 + (lane & 3) * 2;
            #pragma unroll
            for (int f = 0; f < 4; f++) {
                int r0 = wm * 64 + f * 16 + (lane >> 2);
                *(float2*)(stg + r0 * STG_PITCH + col) = make_float2(d[f][g][0], d[f][g][1]);
                *(float2*)(stg + (r0 + 8) * STG_PITCH + col) = make_float2(d[f][g][2], d[f][g][3]);
            }
        }
        __syncthreads();
        {
            const int c = (tid & 31) * 4;
            #pragma unroll
            for (int i = 0; i < 16; i++) {
                int idx = i * 256 + tid;
                int row = idx >> 5;
                int gr = mbase + row;
                if (gr < N_NODES) {
                    float4 v = *(const float4*)(stg + row * STG_PITCH + c);
                    *(float4*)(g_UV + (size_t)gr * 512 + nc * 128 + c) = v;
                }
            }
        }
        __syncthreads();
        if (nc < 3)
            load_B_async_n(smb + OFF_BHI, smb + OFF_BLO,
                           g_nBhi4 + (nc + 1) * CHUNK_U4,
                           g_nBlo4 + (nc + 1) * CHUNK_U4, tid);
    }
}

// ---------------------------------------------------------------------------
// edge kernel: 128x128 tile, 64-k quarter staging, 2 CTAs/SM
// ---------------------------------------------------------------------------
// FIXED: blob rows are 16 uint4 (128 bf16); a 64-k quarter is 8 uint4 per row;
// copy all 128 rows x 8 uint4 = 1024 uint4 each for hi and lo.
__device__ __forceinline__ void edge_load_Bq(uint32_t smb, int q, int tid) {
    const int kc = q >> 1, kh = (q & 1) * 8;     // quarter offset in uint4 units
    #pragma unroll
    for (int i = 0; i < 4; i++) {
        int idx = i * 256 + tid;                  // 0..1023
        int n = idx >> 3, j = idx & 7;
        uint32_t dst = n * EP + j * 16;
        const uint4* sh = g_eBhi4 + kc * CHUNK_U4 + n * 16 + kh + j;
        const uint4* sl = g_eBlo4 + kc * CHUNK_U4 + n * 16 + kh + j;
        cpasync16(smb + EOFF_BH + dst, sh);
        cpasync16(smb + EOFF_BL + dst, sl);
    }
    cp_commit();
}

__device__ __forceinline__ void edge_gather_q(char* sm, const int* ssrc, const int* sdst,
                                              const float* __restrict__ b1,
                                              int q, int buf, int tid) {
    const int row = tid >> 1, h = tid & 1;
    const float* U = g_UV + (size_t)ssrc[row] * 512 + q * 64 + h * 32;
    const float* V = g_UV + (size_t)sdst[row] * 512 + 256 + q * 64 + h * 32;
    const float* Bb = b1 + q * 64 + h * 32;
    char* ah = sm + EOFF_A + buf * 2 * EA_BUF + row * EP + h * 64;
    char* al = ah + EA_BUF;
    #pragma unroll
    for (int i = 0; i < 8; i++) {
        float4 u4 = *(const float4*)(U + i * 4);
        float4 v4 = *(const float4*)(V + i * 4);
        float4 c4 = *(const float4*)(Bb + i * 4);
        float h0 = fmaxf(u4.x + v4.x + c4.x, 0.f);
        float h1 = fmaxf(u4.y + v4.y + c4.y, 0.f);
        float h2 = fmaxf(u4.z + v4.z + c4.z, 0.f);
        float h3 = fmaxf(u4.w + v4.w + c4.w, 0.f);
        uint32_t H0, L0, H1, L1;
        split2(h0, h1, H0, L0);
        split2(h2, h3, H1, L1);
        *(uint2*)(ah + i * 8) = make_uint2(H0, H1);
        *(uint2*)(al + i * 8) = make_uint2(L0, L1);
    }
}

__global__ void __launch_bounds__(256, 2) edge_mma(const void* __restrict__ EI,
                                                   const float* __restrict__ b1,
                                                   const float* __restrict__ b2,
                                                   float* __restrict__ out) {
    extern __shared__ char sm[];
    const uint32_t smb = smem_u32(sm);
    int* ssrc = (int*)(sm + EOFF_IDX);
    int* sdst = ssrc + 128;
    const int tid = threadIdx.x, lane = tid & 31, wid = tid >> 5;
    const int wm = wid & 1, wn = wid >> 1;
    const int ebase = blockIdx.x * 128;

    // prologue: B(0) prefetch, index load, A(0) gather
    edge_load_Bq(smb, 0, tid);
    if (tid < 128) {
        int e = ebase + tid;
        long long s = 0, dd = 0;
        if (e < E_EDGES) {
            if (g_idx64) {
                const long long* p = (const long long*)EI;
                s = p[e]; dd = p[e + E_EDGES];
            } else {
                const int* p = (const int*)EI;
                s = p[e]; dd = p[e + E_EDGES];
            }
        }
        ssrc[tid] = min(max((int)s, 0), N_NODES - 1);
        sdst[tid] = min(max((int)dd, 0), N_NODES - 1);
    }
    __syncthreads();
    edge_gather_q(sm, ssrc, sdst, b1, 0, 0, tid);
    cp_wait0();
    __syncthreads();

    // lane bases
    const int arow = wm * 64 + (lane & 7) + ((lane >> 3) & 1) * 8;
    const uint32_t aOff = arow * EP + ((lane >> 4) & 1) * 16;
    const int bn = wn * 32 + (lane & 7) + ((lane >> 4) & 1) * 8;
    const uint32_t bHi = smb + EOFF_BH + bn * EP + ((lane >> 3) & 1) * 16;
    const uint32_t bLo = smb + EOFF_BL + bn * EP + ((lane >> 3) & 1) * 16;

    float d[4][4][4];
    #pragma unroll
    for (int f = 0; f < 4; f++)
        #pragma unroll
        for (int g = 0; g < 4; g++)
            #pragma unroll
            for (int c = 0; c < 4; c++) d[f][g][c] = 0.f;

    #pragma unroll 1
    for (int q = 0; q < 4; q++) {
        const int buf = q & 1;
        const uint32_t aHi = smb + EOFF_A + buf * 2 * EA_BUF + aOff;
        const uint32_t aLo = aHi + EA_BUF;
        // mma quarter: 4 k-steps; reuse Af regs for hi/lo (register budget 128)
        #pragma unroll
        for (int ks = 0; ks < 4; ks++) {
            uint32_t Af[4][4], Bh[2][4], Bl[2][4];
            #pragma unroll
            for (int gp = 0; gp < 2; gp++) {
                ldsm_x4(Bh[gp], bHi + gp * (16 * EP) + ks * 32);
                ldsm_x4(Bl[gp], bLo + gp * (16 * EP) + ks * 32);
            }
            #pragma unroll
            for (int f = 0; f < 4; f++)
                ldsm_x4(Af[f], aHi + f * (16 * EP) + ks * 32);
            #pragma unroll
            for (int f = 0; f < 4; f++)
                #pragma unroll
                for (int g = 0; g < 4; g++) {
                    mma16816(d[f][g], Af[f], &Bh[g >> 1][(g & 1) * 2]);
                    mma16816(d[f][g], Af[f], &Bl[g >> 1][(g & 1) * 2]);
                }
            #pragma unroll
            for (int f = 0; f < 4; f++)
                ldsm_x4(Af[f], aLo + f * (16 * EP) + ks * 32);
            #pragma unroll
            for (int f = 0; f < 4; f++)
                #pragma unroll
                for (int g = 0; g < 4; g++)
                    mma16816(d[f][g], Af[f], &Bh[g >> 1][(g & 1) * 2]);
        }
        __syncthreads();            // A(q), B(q) consumption complete
        if (q < 3) {
            edge_load_Bq(smb, q + 1, tid);                          // async B(q+1)
            edge_gather_q(sm, ssrc, sdst, b1, q + 1, buf ^ 1, tid); // gather A(q+1)
            cp_wait0();
            __syncthreads();
        }
    }

    // staged, coalesced epilogue with fused b2 (A area is dead)
    float* stg = (float*)(sm + EOFF_A);
    #pragma unroll
    for (int g = 0; g < 4; g++) {
        int col = wn * 32 + g * 8 + (lane & 3) * 2;
        #pragma unroll
        for (int f = 0; f < 4; f++) {
            int r0 = wm * 64 + f * 16 + (lane >> 2);
            *(float2*)(stg + r0 * STG_PITCH + col) = make_float2(d[f][g][0], d[f][g][1]);
            *(float2*)(stg + (r0 + 8) * STG_PITCH + col) = make_float2(d[f][g][2], d[f][g][3]);
        }
    }
    __syncthreads();
    {
        const int c = (tid & 31) * 4;
        float4 bb = *(const float4*)(b2 + c);
        #pragma unroll
        for (int i = 0; i < 16; i++) {
            int idx = i * 256 + tid;
            int row = idx >> 5;
            int e = ebase + row;
            if (e < E_EDGES) {
                float4 v = *(const float4*)(stg + row * STG_PITCH + c);
                *(float4*)(out + (size_t)e * 128 + c) =
                    make_float4(v.x + bb.x, v.y + bb.y, v.z + bb.z, v.w + bb.w);
            }
        }
    }
}

// ---------------------------------------------------------------------------
// launch — inputs resolved by unique element counts
// ---------------------------------------------------------------------------
extern "C" void kernel_launch(void* const* d_in, const int* in_sizes, int n_in,
                              void* d_out, int out_size) {
    const float* z = nullptr;
    const void* ei = nullptr;
    const float* W1 = nullptr;
    const float* b1 = nullptr;
    const float* W2 = nullptr;
    const float* b2 = nullptr;
    for (int i = 0; i < n_in; i++) {
        switch (in_sizes[i]) {
            case 25600000: z = (const float*)d_in[i]; break;
            case 1000000:  ei = d_in[i];              break;
            case 131072:   W1 = (const float*)d_in[i]; break;
            case 256:      b1 = (const float*)d_in[i]; break;
            case 32768:    W2 = (const float*)d_in[i]; break;
            case 128:      b2 = (const float*)d_in[i]; break;
            default: break;
        }
    }
    float* out = (float*)d_out;

    cudaFuncSetAttribute(node_mma, cudaFuncAttributeMaxDynamicSharedMemorySize, SM_BYTES);
    cudaFuncSetAttribute(edge_mma, cudaFuncAttributeMaxDynamicSharedMemorySize, SM_E2);

    detect_kernel<<<1, 32>>>((const unsigned*)ei);
    prep_kernel<<<640, 256>>>(W1, W2);
    node_mma<<<(N_NODES + 127) / 128, 256, SM_BYTES>>>(z);
    edge_mma<<<(E_EDGES + 127) / 128, 256, SM_E2>>>(ei, b1, b2, out);
}

// round 12
// speedup vs baseline: 1.1793x; 1.1377x over previous
#include <cuda_runtime.h>
#include <cuda_bf16.h>
#include <cstdint>

#define N_NODES 100000
#define E_EDGES 500000
#define HSIZE   1024      // src>>7 buckets (782 used)

// ---------------------------------------------------------------------------
// Device scratch
// ---------------------------------------------------------------------------
__device__ float g_UV[(size_t)N_NODES * 512];   // per node: U[0:256], V[256:512]
__device__ uint4 g_nBhi4[16384];                // node B: 8 chunks x 128x128 bf16
__device__ uint4 g_nBlo4[16384];
__device__ uint4 g_eBhi4[4096];                 // edge B (W2): 2 chunks x 128x128 bf16
__device__ uint4 g_eBlo4[4096];
__device__ int   g_idx64;
__device__ int   g_perm[E_EDGES];               // src-locality edge order
__device__ int   g_hist[HSIZE];
__device__ int   g_off[HSIZE];

#define CHUNK_U4 2048   // 128*128 bf16 = 32768 B = 2048 uint4

// ---------------- node kernel smem layout ----------------
#define OFF_AHI  1024
#define OFF_ALO  (1024 + 67584)
#define OFF_BHI  (1024 + 2 * 67584)
#define OFF_BLO  (1024 + 2 * 67584 + 34816)
#define SM_BYTES (1024 + 2 * 67584 + 2 * 34816)   // 205824
#define PITCH_A  528
#define PITCH_B  272
#define STG_PITCH 132

// ---------------- edge kernel smem layout ----------------
#define E_SRC  0
#define E_DST  512
#define E_ID   1024
#define E_AHI  1536
#define E_ALO  (E_AHI + 67584)
#define E_BHI  (E_ALO + 67584)
#define E_BLO  (E_BHI + 34816)
#define SM_E   (E_BLO + 34816)    // 206336

__device__ __forceinline__ uint32_t smem_u32(const void* p) {
    uint32_t a;
    asm("{ .reg .u64 t; cvta.to.shared.u64 t, %1; cvt.u32.u64 %0, t; }" : "=r"(a) : "l"(p));
    return a;
}

__device__ __forceinline__ void ldsm_x4(uint32_t* r, uint32_t addr) {
    asm volatile("ldmatrix.sync.aligned.m8n8.x4.shared.b16 {%0,%1,%2,%3}, [%4];"
                 : "=r"(r[0]), "=r"(r[1]), "=r"(r[2]), "=r"(r[3]) : "r"(addr));
}

__device__ __forceinline__ void mma16816(float* d, const uint32_t* a, const uint32_t* b) {
    asm volatile(
        "mma.sync.aligned.m16n8k16.row.col.f32.bf16.bf16.f32 "
        "{%0,%1,%2,%3},{%4,%5,%6,%7},{%8,%9},{%0,%1,%2,%3};"
        : "+f"(d[0]), "+f"(d[1]), "+f"(d[2]), "+f"(d[3])
        : "r"(a[0]), "r"(a[1]), "r"(a[2]), "r"(a[3]), "r"(b[0]), "r"(b[1]));
}

__device__ __forceinline__ void cpasync16(uint32_t saddr, const void* g) {
    asm volatile("cp.async.ca.shared.global [%0], [%1], 16;" :: "r"(saddr), "l"(g));
}
__device__ __forceinline__ void cp_commit() { asm volatile("cp.async.commit_group;"); }
__device__ __forceinline__ void cp_wait0()  { asm volatile("cp.async.wait_group 0;" ::: "memory"); }

// packed bf16 split: 2 cvt.bf16x2 + 2 sub + shift/and (vs 4 scalar cvt + 2 cvt)
__device__ __forceinline__ void split2(float a, float b, uint32_t& hi, uint32_t& lo) {
    uint32_t h;
    asm("cvt.rn.bf16x2.f32 %0, %1, %2;" : "=r"(h) : "f"(b), "f"(a));
    float ah = __uint_as_float(h << 16);
    float bh = __uint_as_float(h & 0xFFFF0000u);
    uint32_t l;
    asm("cvt.rn.bf16x2.f32 %0, %1, %2;" : "=r"(l) : "f"(b - bh), "f"(a - ah));
    hi = h;
    lo = l;
}

// ---------------------------------------------------------------------------
// detect edge_index dtype (int64 vs int32)
// ---------------------------------------------------------------------------
__global__ void detect_kernel(const unsigned* __restrict__ ei) {
    if (threadIdx.x == 0 && blockIdx.x == 0) {
        int ok = 1;
        #pragma unroll 1
        for (int i = 0; i < 256; i++)
            if (ei[2 * i + 1] != 0u) { ok = 0; break; }
        g_idx64 = ok;
    }
}

// ---------------------------------------------------------------------------
// src-locality permutation: histogram -> scan -> scatter
// ---------------------------------------------------------------------------
__global__ void zero_hist() {
    int t = blockIdx.x * blockDim.x + threadIdx.x;
    if (t < HSIZE) g_hist[t] = 0;
}

__device__ __forceinline__ int load_src(const void* EI, int e) {
    int s;
    if (g_idx64) s = (int)((const long long*)EI)[e];
    else         s = ((const int*)EI)[e];
    return min(max(s, 0), N_NODES - 1);
}

__global__ void hist_kernel(const void* __restrict__ EI) {
    int e = blockIdx.x * blockDim.x + threadIdx.x;
    if (e < E_EDGES) atomicAdd(&g_hist[load_src(EI, e) >> 7], 1);
}

__global__ void scan_kernel() {
    __shared__ int s[HSIZE];
    int t = threadIdx.x;
    int orig = g_hist[t];
    s[t] = orig;
    __syncthreads();
    #pragma unroll 1
    for (int o = 1; o < HSIZE; o <<= 1) {
        int v = (t >= o) ? s[t - o] : 0;
        __syncthreads();
        s[t] += v;
        __syncthreads();
    }
    g_off[t] = s[t] - orig;   // exclusive prefix
}

__global__ void scatter_kernel(const void* __restrict__ EI) {
    int e = blockIdx.x * blockDim.x + threadIdx.x;
    if (e < E_EDGES) {
        int b = load_src(EI, e) >> 7;
        int pos = atomicAdd(&g_off[b], 1);
        g_perm[pos] = e;
    }
}

// ---------------------------------------------------------------------------
// prep: split weights into bf16 hi/lo chunk blobs [chunk][row][k] (128x128)
// ---------------------------------------------------------------------------
__global__ void prep_kernel(const float* __restrict__ W1, const float* __restrict__ W2) {
    int idx = blockIdx.x * blockDim.x + threadIdx.x;
    float v;
    uint32_t off;
    __nv_bfloat16 *dh, *dl;
    if (idx < 131072) {
        int j = idx >> 8, k = idx & 255;
        v = (j < 256) ? W1[j * 512 + k] : W1[(j - 256) * 512 + 256 + k];
        int nc = j >> 7, row = j & 127, kc = k >> 7, kp = k & 127;
        off = (uint32_t)(kc * 4 + nc) * 16384u + row * 128 + kp;
        dh = (__nv_bfloat16*)g_nBhi4; dl = (__nv_bfloat16*)g_nBlo4;
    } else {
        int e = idx - 131072;
        if (e >= 32768) return;
        int n = e >> 8, k = e & 255;
        v = W2[n * 256 + k];
        int kc = k >> 7, kp = k & 127;
        off = (uint32_t)kc * 16384u + n * 128 + kp;
        dh = (__nv_bfloat16*)g_eBhi4; dl = (__nv_bfloat16*)g_eBlo4;
    }
    __nv_bfloat16 h = __float2bfloat16_rn(v);
    dh[off] = h;
    dl[off] = __float2bfloat16_rn(v - __bfloat162float(h));
}

// ---------------------------------------------------------------------------
// shared helpers
// ---------------------------------------------------------------------------
__device__ __forceinline__ void load_B_async(uint32_t smB_hi, uint32_t smB_lo,
                                             const uint4* srcH, const uint4* srcL, int tid) {
    #pragma unroll
    for (int i = 0; i < 8; i++) {
        int idx = i * 256 + tid;
        int row = idx >> 4, c = idx & 15;
        uint32_t d = row * PITCH_B + c * 16;
        cpasync16(smB_hi + d, srcH + idx);
        cpasync16(smB_lo + d, srcL + idx);
    }
    cp_commit();
}

__device__ __forceinline__ void mma_chunk(float d[4][4][4],
                                          uint32_t aHiBase, uint32_t aLoBase,
                                          uint32_t bHiBase, uint32_t bLoBase) {
    #pragma unroll 1
    for (int ks = 0; ks < 8; ks++) {
        uint32_t Ah[4][4], Al[4][4], Bh[2][4], Bl[2][4];
        #pragma unroll
        for (int f = 0; f < 4; f++) {
            ldsm_x4(Ah[f], aHiBase + f * (16 * PITCH_A) + ks * 32);
            ldsm_x4(Al[f], aLoBase + f * (16 * PITCH_A) + ks * 32);
        }
        #pragma unroll
        for (int gp = 0; gp < 2; gp++) {
            ldsm_x4(Bh[gp], bHiBase + gp * (16 * PITCH_B) + ks * 32);
            ldsm_x4(Bl[gp], bLoBase + gp * (16 * PITCH_B) + ks * 32);
        }
        #pragma unroll
        for (int f = 0; f < 4; f++)
            #pragma unroll
            for (int g = 0; g < 4; g++) {
                const uint32_t* bh = &Bh[g >> 1][(g & 1) * 2];
                const uint32_t* bl = &Bl[g >> 1][(g & 1) * 2];
                mma16816(d[f][g], Ah[f], bh);
                mma16816(d[f][g], Ah[f], bl);
                mma16816(d[f][g], Al[f], bh);
            }
    }
}

__device__ __forceinline__ uint32_t a_lane_base(uint32_t smA, int wm, int lane) {
    int row = wm * 64 + (lane & 7) + ((lane >> 3) & 1) * 8;
    return smA + row * PITCH_A + ((lane >> 4) & 1) * 16;
}
__device__ __forceinline__ uint32_t b_lane_base(uint32_t smB, int wn, int lane) {
    int n = wn * 32 + (lane & 7) + ((lane >> 4) & 1) * 8;
    return smB + n * PITCH_B + ((lane >> 3) & 1) * 16;
}

__device__ __forceinline__ void stage_acc(float* stg, float d[4][4][4],
                                          int wm, int wn, int lane) {
    #pragma unroll
    for (int g = 0; g < 4; g++) {
        int col = wn * 32 + g * 8 + (lane & 3) * 2;
        #pragma unroll
        for (int f = 0; f < 4; f++) {
            int r0 = wm * 64 + f * 16 + (lane >> 2);
            *(float2*)(stg + r0 * STG_PITCH + col) = make_float2(d[f][g][0], d[f][g][1]);
            *(float2*)(stg + (r0 + 8) * STG_PITCH + col) = make_float2(d[f][g][2], d[f][g][3]);
        }
    }
}

// ---------------------------------------------------------------------------
// node kernel: UV[tile of 128 nodes, 512] = Z @ B^T (3-pass bf16 mma.sync)
// ---------------------------------------------------------------------------
__global__ void __launch_bounds__(256, 1) node_mma(const float* __restrict__ Z) {
    extern __shared__ char sm[];
    const uint32_t smb = smem_u32(sm);
    const int tid = threadIdx.x, lane = tid & 31, wid = tid >> 5;
    const int wm = wid & 1, wn = wid >> 1;
    const int mbase = blockIdx.x * 128;

    load_B_async(smb + OFF_BHI, smb + OFF_BLO, g_nBhi4, g_nBlo4, tid);

    {
        const int lrow = tid >> 3;
        const int lk = (tid & 7) * 4;
        #pragma unroll 1
        for (int s = 0; s < 4; s++) {
            int row = s * 32 + lrow;
            int gr = min(mbase + row, N_NODES - 1);
            const float* zr = Z + (size_t)gr * 256;
            char* ah = sm + OFF_AHI + row * PITCH_A;
            char* al = sm + OFF_ALO + row * PITCH_A;
            #pragma unroll
            for (int i = 0; i < 8; i++) {
                int k = lk + i * 32;
                float4 z4 = *(const float4*)(zr + k);
                uint32_t h0, l0, h1, l1;
                split2(z4.x, z4.y, h0, l0);
                split2(z4.z, z4.w, h1, l1);
                *(uint2*)(ah + k * 2) = make_uint2(h0, h1);
                *(uint2*)(al + k * 2) = make_uint2(l0, l1);
            }
        }
    }

    const uint32_t aHi = a_lane_base(smb + OFF_AHI, wm, lane);
    const uint32_t aLo = a_lane_base(smb + OFF_ALO, wm, lane);
    const uint32_t bHi = b_lane_base(smb + OFF_BHI, wn, lane);
    const uint32_t bLo = b_lane_base(smb + OFF_BLO, wn, lane);
    float* stg = (float*)(sm + OFF_BHI);

    #pragma unroll 1
    for (int nc = 0; nc < 4; nc++) {
        float d[4][4][4];
        #pragma unroll
        for (int f = 0; f < 4; f++)
            #pragma unroll
            for (int g = 0; g < 4; g++)
                #pragma unroll
                for (int c = 0; c < 4; c++) d[f][g][c] = 0.f;

        #pragma unroll 1
        for (int kc = 0; kc < 2; kc++) {
            cp_wait0();
            __syncthreads();
            mma_chunk(d, aHi + kc * 256, aLo + kc * 256, bHi, bLo);
            __syncthreads();
            if (kc == 0)
                load_B_async(smb + OFF_BHI, smb + OFF_BLO,
                             g_nBhi4 + (1 * 4 + nc) * CHUNK_U4,
                             g_nBlo4 + (1 * 4 + nc) * CHUNK_U4, tid);
        }

        stage_acc(stg, d, wm, wn, lane);
        __syncthreads();
        {
            const int c = (tid & 31) * 4;
            #pragma unroll
            for (int i = 0; i < 16; i++) {
                int idx = i * 256 + tid;
                int row = idx >> 5;
                int gr = mbase + row;
                if (gr < N_NODES) {
                    float4 v = *(const float4*)(stg + row * STG_PITCH + c);
                    *(float4*)(g_UV + (size_t)gr * 512 + nc * 128 + c) = v;
                }
            }
        }
        __syncthreads();
        if (nc < 3)
            load_B_async(smb + OFF_BHI, smb + OFF_BLO,
                         g_nBhi4 + (nc + 1) * CHUNK_U4,
                         g_nBlo4 + (nc + 1) * CHUNK_U4, tid);
    }
}

// ---------------------------------------------------------------------------
// edge kernel: tiles follow g_perm (src-locality order)
// ---------------------------------------------------------------------------
__global__ void __launch_bounds__(256, 1) edge_mma(const void* __restrict__ EI,
                                                   const float* __restrict__ b1,
                                                   const float* __restrict__ b2,
                                                   float* __restrict__ out) {
    extern __shared__ char sm[];
    const uint32_t smb = smem_u32(sm);
    int* ssrc = (int*)(sm + E_SRC);
    int* sdst = (int*)(sm + E_DST);
    int* sid  = (int*)(sm + E_ID);
    const int tid = threadIdx.x, lane = tid & 31, wid = tid >> 5;
    const int wm = wid & 1, wn = wid >> 1;
    const int ebase = blockIdx.x * 128;

    // prefetch first B chunk — overlaps index load + gather
    load_B_async(smb + E_BHI, smb + E_BLO, g_eBhi4, g_eBlo4, tid);

    if (tid < 128) {
        int e = min(ebase + tid, E_EDGES - 1);
        int id = g_perm[e];
        long long s, dd;
        if (g_idx64) {
            const long long* p = (const long long*)EI;
            s = p[id]; dd = p[id + E_EDGES];
        } else {
            const int* p = (const int*)EI;
            s = p[id]; dd = p[id + E_EDGES];
        }
        ssrc[tid] = min(max((int)s, 0), N_NODES - 1);
        sdst[tid] = min(max((int)dd, 0), N_NODES - 1);
        sid[tid] = id;
    }
    __syncthreads();

    // --- stage A: gather U[src]+V[dst]+b1, relu, split, full K=256 ---
    {
        const int lrow = tid >> 3;
        const int lk = (tid & 7) * 4;
        #pragma unroll 1
        for (int s = 0; s < 4; s++) {
            int row = s * 32 + lrow;
            const float* Ur = g_UV + (size_t)ssrc[row] * 512;
            const float* Vr = g_UV + (size_t)sdst[row] * 512 + 256;
            char* ah = sm + E_AHI + row * PITCH_A;
            char* al = sm + E_ALO + row * PITCH_A;
            #pragma unroll
            for (int i = 0; i < 8; i++) {
                int k = lk + i * 32;
                float4 u4 = *(const float4*)(Ur + k);
                float4 v4 = *(const float4*)(Vr + k);
                float4 c4 = *(const float4*)(b1 + k);
                float h0 = fmaxf(u4.x + v4.x + c4.x, 0.f);
                float h1 = fmaxf(u4.y + v4.y + c4.y, 0.f);
                float h2 = fmaxf(u4.z + v4.z + c4.z, 0.f);
                float h3 = fmaxf(u4.w + v4.w + c4.w, 0.f);
                uint32_t H0, L0, H1, L1;
                split2(h0, h1, H0, L0);
                split2(h2, h3, H1, L1);
                *(uint2*)(ah + k * 2) = make_uint2(H0, H1);
                *(uint2*)(al + k * 2) = make_uint2(L0, L1);
            }
        }
    }

    const uint32_t aHi = a_lane_base(smb + E_AHI, wm, lane);
    const uint32_t aLo = a_lane_base(smb + E_ALO, wm, lane);
    const uint32_t bHi = b_lane_base(smb + E_BHI, wn, lane);
    const uint32_t bLo = b_lane_base(smb + E_BLO, wn, lane);
    float* stg = (float*)(sm + E_BHI);

    float d[4][4][4];
    #pragma unroll
    for (int f = 0; f < 4; f++)
        #pragma unroll
        for (int g = 0; g < 4; g++)
            #pragma unroll
            for (int c = 0; c < 4; c++) d[f][g][c] = 0.f;

    #pragma unroll 1
    for (int kc = 0; kc < 2; kc++) {
        cp_wait0();
        __syncthreads();
        mma_chunk(d, aHi + kc * 256, aLo + kc * 256, bHi, bLo);
        __syncthreads();
        if (kc == 0)
            load_B_async(smb + E_BHI, smb + E_BLO,
                         g_eBhi4 + CHUNK_U4, g_eBlo4 + CHUNK_U4, tid);
    }

    // --- staged, coalesced epilogue with fused b2, scattered by sid ---
    stage_acc(stg, d, wm, wn, lane);
    __syncthreads();
    {
        const int c = (tid & 31) * 4;
        float4 bb = *(const float4*)(b2 + c);
        #pragma unroll
        for (int i = 0; i < 16; i++) {
            int idx = i * 256 + tid;
            int row = idx >> 5;
            if (ebase + row < E_EDGES || true) {
                int id = sid[row];
                float4 v = *(const float4*)(stg + row * STG_PITCH + c);
                *(float4*)(out + (size_t)id * 128 + c) =
                    make_float4(v.x + bb.x, v.y + bb.y, v.z + bb.z, v.w + bb.w);
            }
        }
    }
}

// ---------------------------------------------------------------------------
// launch — inputs resolved by unique element counts
// ---------------------------------------------------------------------------
extern "C" void kernel_launch(void* const* d_in, const int* in_sizes, int n_in,
                              void* d_out, int out_size) {
    const float* z = nullptr;
    const void* ei = nullptr;
    const float* W1 = nullptr;
    const float* b1 = nullptr;
    const float* W2 = nullptr;
    const float* b2 = nullptr;
    for (int i = 0; i < n_in; i++) {
        switch (in_sizes[i]) {
            case 25600000: z = (const float*)d_in[i]; break;
            case 1000000:  ei = d_in[i];              break;
            case 131072:   W1 = (const float*)d_in[i]; break;
            case 256:      b1 = (const float*)d_in[i]; break;
            case 32768:    W2 = (const float*)d_in[i]; break;
            case 128:      b2 = (const float*)d_in[i]; break;
            default: break;
        }
    }
    float* out = (float*)d_out;

    cudaFuncSetAttribute(node_mma, cudaFuncAttributeMaxDynamicSharedMemorySize, SM_BYTES);
    cudaFuncSetAttribute(edge_mma, cudaFuncAttributeMaxDynamicSharedMemorySize, SM_E);

    detect_kernel<<<1, 32>>>((const unsigned*)ei);
    zero_hist<<<4, 256>>>();
    hist_kernel<<<(E_EDGES + 255) / 256, 256>>>(ei);
    scan_kernel<<<1, HSIZE>>>();
    scatter_kernel<<<(E_EDGES + 255) / 256, 256>>>(ei);
    prep_kernel<<<640, 256>>>(W1, W2);
    node_mma<<<(N_NODES + 127) / 128, 256, SM_BYTES>>>(z);
    edge_mma<<<(E_EDGES + 127) / 128, 256, SM_E>>>(ei, b1, b2, out);
}

// round 13
// speedup vs baseline: 1.3907x; 1.1792x over previous
#include <cuda_runtime.h>
#include <cuda_bf16.h>
#include <cstdint>

#define N_NODES 100000
#define E_EDGES 500000

// ---------------------------------------------------------------------------
// Device scratch
// ---------------------------------------------------------------------------
__device__ uint4 g_UVq4[(size_t)N_NODES * 64];  // int16 UV rows: [node][512] (U 0:256, V 256:512)
__device__ float g_sc[N_NODES * 4];             // per (node, 128-col chunk) scale
__device__ uint4 g_nBhi4[16384];                // node B: 8 chunks x 128x128 bf16
__device__ uint4 g_nBlo4[16384];
__device__ uint4 g_eBhi4[4096];                 // edge B (W2): 2 chunks x 128x128 bf16
__device__ uint4 g_eBlo4[4096];
__device__ int   g_idx64;

#define CHUNK_U4 2048   // 128*128 bf16 = 32768 B = 2048 uint4

// ---------------- node kernel smem layout ----------------
#define OFF_AHI  1024
#define OFF_ALO  (1024 + 67584)
#define OFF_BHI  (1024 + 2 * 67584)
#define OFF_BLO  (1024 + 2 * 67584 + 34816)
#define SM_BYTES (1024 + 2 * 67584 + 2 * 34816)   // 205824
#define PITCH_A  528
#define PITCH_B  272
#define STG_PITCH 132

// ---------------- edge kernel smem layout ----------------
#define E_SRC  0
#define E_DST  512
#define E_AHI  1536
#define E_ALO  (E_AHI + 67584)
#define E_BHI  (E_ALO + 67584)
#define E_BLO  (E_BHI + 34816)
#define SM_E   (E_BLO + 34816)    // 206336

__device__ __forceinline__ uint32_t smem_u32(const void* p) {
    uint32_t a;
    asm("{ .reg .u64 t; cvta.to.shared.u64 t, %1; cvt.u32.u64 %0, t; }" : "=r"(a) : "l"(p));
    return a;
}

__device__ __forceinline__ void ldsm_x4(uint32_t* r, uint32_t addr) {
    asm volatile("ldmatrix.sync.aligned.m8n8.x4.shared.b16 {%0,%1,%2,%3}, [%4];"
                 : "=r"(r[0]), "=r"(r[1]), "=r"(r[2]), "=r"(r[3]) : "r"(addr));
}

__device__ __forceinline__ void mma16816(float* d, const uint32_t* a, const uint32_t* b) {
    asm volatile(
        "mma.sync.aligned.m16n8k16.row.col.f32.bf16.bf16.f32 "
        "{%0,%1,%2,%3},{%4,%5,%6,%7},{%8,%9},{%0,%1,%2,%3};"
        : "+f"(d[0]), "+f"(d[1]), "+f"(d[2]), "+f"(d[3])
        : "r"(a[0]), "r"(a[1]), "r"(a[2]), "r"(a[3]), "r"(b[0]), "r"(b[1]));
}

__device__ __forceinline__ void cpasync16(uint32_t saddr, const void* g) {
    asm volatile("cp.async.ca.shared.global [%0], [%1], 16;" :: "r"(saddr), "l"(g));
}
__device__ __forceinline__ void cp_commit() { asm volatile("cp.async.commit_group;"); }
__device__ __forceinline__ void cp_wait0()  { asm volatile("cp.async.wait_group 0;" ::: "memory"); }

// packed bf16 split (R12, verified)
__device__ __forceinline__ void split2(float a, float b, uint32_t& hi, uint32_t& lo) {
    uint32_t h;
    asm("cvt.rn.bf16x2.f32 %0, %1, %2;" : "=r"(h) : "f"(b), "f"(a));
    float ah = __uint_as_float(h << 16);
    float bh = __uint_as_float(h & 0xFFFF0000u);
    uint32_t l;
    asm("cvt.rn.bf16x2.f32 %0, %1, %2;" : "=r"(l) : "f"(b - bh), "f"(a - ah));
    hi = h;
    lo = l;
}

// dequantize 8 int16 (one uint4) with scale s
__device__ __forceinline__ void dq8(uint4 p, float s, float* f) {
    f[0] = (float)((short)(p.x & 0xFFFF)) * s; f[1] = (float)(((int)p.x) >> 16) * s;
    f[2] = (float)((short)(p.y & 0xFFFF)) * s; f[3] = (float)(((int)p.y) >> 16) * s;
    f[4] = (float)((short)(p.z & 0xFFFF)) * s; f[5] = (float)(((int)p.z) >> 16) * s;
    f[6] = (float)((short)(p.w & 0xFFFF)) * s; f[7] = (float)(((int)p.w) >> 16) * s;
}

__device__ __forceinline__ uint32_t pk16(float a, float b) {
    int ia = __float2int_rn(a), ib = __float2int_rn(b);
    return (uint32_t)(ia & 0xFFFF) | ((uint32_t)ib << 16);
}

// ---------------------------------------------------------------------------
// detect edge_index dtype (int64 vs int32)
// ---------------------------------------------------------------------------
__global__ void detect_kernel(const unsigned* __restrict__ ei) {
    if (threadIdx.x == 0 && blockIdx.x == 0) {
        int ok = 1;
        #pragma unroll 1
        for (int i = 0; i < 256; i++)
            if (ei[2 * i + 1] != 0u) { ok = 0; break; }
        g_idx64 = ok;
    }
}

// ---------------------------------------------------------------------------
// prep: split weights into bf16 hi/lo chunk blobs [chunk][row][k] (128x128)
// ---------------------------------------------------------------------------
__global__ void prep_kernel(const float* __restrict__ W1, const float* __restrict__ W2) {
    int idx = blockIdx.x * blockDim.x + threadIdx.x;
    float v;
    uint32_t off;
    __nv_bfloat16 *dh, *dl;
    if (idx < 131072) {
        int j = idx >> 8, k = idx & 255;
        v = (j < 256) ? W1[j * 512 + k] : W1[(j - 256) * 512 + 256 + k];
        int nc = j >> 7, row = j & 127, kc = k >> 7, kp = k & 127;
        off = (uint32_t)(kc * 4 + nc) * 16384u + row * 128 + kp;
        dh = (__nv_bfloat16*)g_nBhi4; dl = (__nv_bfloat16*)g_nBlo4;
    } else {
        int e = idx - 131072;
        if (e >= 32768) return;
        int n = e >> 8, k = e & 255;
        v = W2[n * 256 + k];
        int kc = k >> 7, kp = k & 127;
        off = (uint32_t)kc * 16384u + n * 128 + kp;
        dh = (__nv_bfloat16*)g_eBhi4; dl = (__nv_bfloat16*)g_eBlo4;
    }
    __nv_bfloat16 h = __float2bfloat16_rn(v);
    dh[off] = h;
    dl[off] = __float2bfloat16_rn(v - __bfloat162float(h));
}

// ---------------------------------------------------------------------------
// shared helpers
// ---------------------------------------------------------------------------
__device__ __forceinline__ void load_B_async(uint32_t smB_hi, uint32_t smB_lo,
                                             const uint4* srcH, const uint4* srcL, int tid) {
    #pragma unroll
    for (int i = 0; i < 8; i++) {
        int idx = i * 256 + tid;
        int row = idx >> 4, c = idx & 15;
        uint32_t d = row * PITCH_B + c * 16;
        cpasync16(smB_hi + d, srcH + idx);
        cpasync16(smB_lo + d, srcL + idx);
    }
    cp_commit();
}

__device__ __forceinline__ void mma_chunk(float d[4][4][4],
                                          uint32_t aHiBase, uint32_t aLoBase,
                                          uint32_t bHiBase, uint32_t bLoBase) {
    #pragma unroll 1
    for (int ks = 0; ks < 8; ks++) {
        uint32_t Ah[4][4], Al[4][4], Bh[2][4], Bl[2][4];
        #pragma unroll
        for (int f = 0; f < 4; f++) {
            ldsm_x4(Ah[f], aHiBase + f * (16 * PITCH_A) + ks * 32);
            ldsm_x4(Al[f], aLoBase + f * (16 * PITCH_A) + ks * 32);
        }
        #pragma unroll
        for (int gp = 0; gp < 2; gp++) {
            ldsm_x4(Bh[gp], bHiBase + gp * (16 * PITCH_B) + ks * 32);
            ldsm_x4(Bl[gp], bLoBase + gp * (16 * PITCH_B) + ks * 32);
        }
        #pragma unroll
        for (int f = 0; f < 4; f++)
            #pragma unroll
            for (int g = 0; g < 4; g++) {
                const uint32_t* bh = &Bh[g >> 1][(g & 1) * 2];
                const uint32_t* bl = &Bl[g >> 1][(g & 1) * 2];
                mma16816(d[f][g], Ah[f], bh);
                mma16816(d[f][g], Ah[f], bl);
                mma16816(d[f][g], Al[f], bh);
            }
    }
}

__device__ __forceinline__ uint32_t a_lane_base(uint32_t smA, int wm, int lane) {
    int row = wm * 64 + (lane & 7) + ((lane >> 3) & 1) * 8;
    return smA + row * PITCH_A + ((lane >> 4) & 1) * 16;
}
__device__ __forceinline__ uint32_t b_lane_base(uint32_t smB, int wn, int lane) {
    int n = wn * 32 + (lane & 7) + ((lane >> 4) & 1) * 8;
    return smB + n * PITCH_B + ((lane >> 3) & 1) * 16;
}

__device__ __forceinline__ void stage_acc(float* stg, float d[4][4][4],
                                          int wm, int wn, int lane) {
    #pragma unroll
    for (int g = 0; g < 4; g++) {
        int col = wn * 32 + g * 8 + (lane & 3) * 2;
        #pragma unroll
        for (int f = 0; f < 4; f++) {
            int r0 = wm * 64 + f * 16 + (lane >> 2);
            *(float2*)(stg + r0 * STG_PITCH + col) = make_float2(d[f][g][0], d[f][g][1]);
            *(float2*)(stg + (r0 + 8) * STG_PITCH + col) = make_float2(d[f][g][2], d[f][g][3]);
        }
    }
}

// ---------------------------------------------------------------------------
// node kernel: computes UV tile, then quantizes to int16 + per-(row,nc) scale
// ---------------------------------------------------------------------------
__global__ void __launch_bounds__(256, 1) node_mma(const float* __restrict__ Z) {
    extern __shared__ char sm[];
    const uint32_t smb = smem_u32(sm);
    const int tid = threadIdx.x, lane = tid & 31, wid = tid >> 5;
    const int wm = wid & 1, wn = wid >> 1;
    const int mbase = blockIdx.x * 128;

    load_B_async(smb + OFF_BHI, smb + OFF_BLO, g_nBhi4, g_nBlo4, tid);

    // --- stage A: load Z rows, split to bf16 hi/lo, full K=256 resident ---
    {
        const int lrow = tid >> 3;
        const int lk = (tid & 7) * 4;
        #pragma unroll 1
        for (int s = 0; s < 4; s++) {
            int row = s * 32 + lrow;
            int gr = min(mbase + row, N_NODES - 1);
            const float* zr = Z + (size_t)gr * 256;
            char* ah = sm + OFF_AHI + row * PITCH_A;
            char* al = sm + OFF_ALO + row * PITCH_A;
            #pragma unroll
            for (int i = 0; i < 8; i++) {
                int k = lk + i * 32;
                float4 z4 = *(const float4*)(zr + k);
                uint32_t h0, l0, h1, l1;
                split2(z4.x, z4.y, h0, l0);
                split2(z4.z, z4.w, h1, l1);
                *(uint2*)(ah + k * 2) = make_uint2(h0, h1);
                *(uint2*)(al + k * 2) = make_uint2(l0, l1);
            }
        }
    }

    const uint32_t aHi = a_lane_base(smb + OFF_AHI, wm, lane);
    const uint32_t aLo = a_lane_base(smb + OFF_ALO, wm, lane);
    const uint32_t bHi = b_lane_base(smb + OFF_BHI, wn, lane);
    const uint32_t bLo = b_lane_base(smb + OFF_BLO, wn, lane);
    float* stg = (float*)(sm + OFF_BHI);

    #pragma unroll 1
    for (int nc = 0; nc < 4; nc++) {
        float d[4][4][4];
        #pragma unroll
        for (int f = 0; f < 4; f++)
            #pragma unroll
            for (int g = 0; g < 4; g++)
                #pragma unroll
                for (int c = 0; c < 4; c++) d[f][g][c] = 0.f;

        #pragma unroll 1
        for (int kc = 0; kc < 2; kc++) {
            cp_wait0();
            __syncthreads();
            mma_chunk(d, aHi + kc * 256, aLo + kc * 256, bHi, bLo);
            __syncthreads();
            if (kc == 0)
                load_B_async(smb + OFF_BHI, smb + OFF_BLO,
                             g_nBhi4 + (1 * 4 + nc) * CHUNK_U4,
                             g_nBlo4 + (1 * 4 + nc) * CHUNK_U4, tid);
        }

        // --- stage + quantize epilogue (B area is dead) ---
        stage_acc(stg, d, wm, wn, lane);
        __syncthreads();
        {
            const int row = tid >> 1, h = tid & 1;
            const int node = mbase + row;
            // per-row absmax over this 128-col chunk (2 threads/row)
            float mx = 0.f;
            const float* sp = stg + row * STG_PITCH + h * 64;
            #pragma unroll
            for (int c = 0; c < 64; c++) mx = fmaxf(mx, fabsf(sp[c]));
            mx = fmaxf(mx, __shfl_xor_sync(0xFFFFFFFFu, mx, 1));
            float scale = (mx > 1e-30f) ? mx * (1.f / 32704.f) : 1.f;
            float inv = 1.f / scale;
            if (h == 0 && node < N_NODES) g_sc[node * 4 + nc] = scale;
            if (node < N_NODES) {
                uint4* dst = g_UVq4 + (size_t)node * 64 + nc * 16 + h * 8;
                #pragma unroll
                for (int u = 0; u < 8; u++) {
                    const float* q = sp + u * 8;
                    uint4 pq;
                    pq.x = pk16(q[0] * inv, q[1] * inv);
                    pq.y = pk16(q[2] * inv, q[3] * inv);
                    pq.z = pk16(q[4] * inv, q[5] * inv);
                    pq.w = pk16(q[6] * inv, q[7] * inv);
                    dst[u] = pq;
                }
            }
        }
        __syncthreads();
        if (nc < 3)
            load_B_async(smb + OFF_BHI, smb + OFF_BLO,
                         g_nBhi4 + (nc + 1) * CHUNK_U4,
                         g_nBlo4 + (nc + 1) * CHUNK_U4, tid);
    }
}

// ---------------------------------------------------------------------------
// edge kernel: out[128 edges, 128] = relu(U[src]+V[dst]+b1) @ W2^T + b2
// gathers int16 UV + per-chunk scales
// ---------------------------------------------------------------------------
__global__ void __launch_bounds__(256, 1) edge_mma(const void* __restrict__ EI,
                                                   const float* __restrict__ b1,
                                                   const float* __restrict__ b2,
                                                   float* __restrict__ out) {
    extern __shared__ char sm[];
    const uint32_t smb = smem_u32(sm);
    int* ssrc = (int*)(sm + E_SRC);
    int* sdst = (int*)(sm + E_DST);
    const int tid = threadIdx.x, lane = tid & 31, wid = tid >> 5;
    const int wm = wid & 1, wn = wid >> 1;
    const int ebase = blockIdx.x * 128;

    load_B_async(smb + E_BHI, smb + E_BLO, g_eBhi4, g_eBlo4, tid);

    if (tid < 128) {
        int e = ebase + tid;
        long long s = 0, dd = 0;
        if (e < E_EDGES) {
            if (g_idx64) {
                const long long* p = (const long long*)EI;
                s = p[e]; dd = p[e + E_EDGES];
            } else {
                const int* p = (const int*)EI;
                s = p[e]; dd = p[e + E_EDGES];
            }
        }
        ssrc[tid] = min(max((int)s, 0), N_NODES - 1);
        sdst[tid] = min(max((int)dd, 0), N_NODES - 1);
    }
    __syncthreads();

    // --- stage A: gather int16 U/V, dequant, +b1, relu, split ---
    {
        const int lrow = tid >> 3;
        const int j = tid & 7;
        #pragma unroll 1
        for (int s = 0; s < 4; s++) {
            int row = s * 32 + lrow;
            int src = ssrc[row], dst = sdst[row];
            const uint4* Uq = g_UVq4 + (size_t)src * 64;
            const uint4* Vq = g_UVq4 + (size_t)dst * 64 + 32;
            float su0 = g_sc[src * 4 + 0], su1 = g_sc[src * 4 + 1];
            float sv0 = g_sc[dst * 4 + 2], sv1 = g_sc[dst * 4 + 3];
            char* ah = sm + E_AHI + row * PITCH_A;
            char* al = sm + E_ALO + row * PITCH_A;
            #pragma unroll
            for (int i = 0; i < 4; i++) {
                int k = j * 8 + i * 64;
                uint4 up = Uq[j + i * 8];
                uint4 vp = Vq[j + i * 8];
                float su = (i < 2) ? su0 : su1;
                float sv = (i < 2) ? sv0 : sv1;
                float uu[8], vv[8];
                dq8(up, su, uu);
                dq8(vp, sv, vv);
                float4 c0 = *(const float4*)(b1 + k);
                float4 c1 = *(const float4*)(b1 + k + 4);
                float h0 = fmaxf(uu[0] + vv[0] + c0.x, 0.f);
                float h1 = fmaxf(uu[1] + vv[1] + c0.y, 0.f);
                float h2 = fmaxf(uu[2] + vv[2] + c0.z, 0.f);
                float h3 = fmaxf(uu[3] + vv[3] + c0.w, 0.f);
                float h4 = fmaxf(uu[4] + vv[4] + c1.x, 0.f);
                float h5 = fmaxf(uu[5] + vv[5] + c1.y, 0.f);
                float h6 = fmaxf(uu[6] + vv[6] + c1.z, 0.f);
                float h7 = fmaxf(uu[7] + vv[7] + c1.w, 0.f);
                uint4 hi, lo;
                split2(h0, h1, hi.x, lo.x);
                split2(h2, h3, hi.y, lo.y);
                split2(h4, h5, hi.z, lo.z);
                split2(h6, h7, hi.w, lo.w);
                *(uint4*)(ah + k * 2) = hi;
                *(uint4*)(al + k * 2) = lo;
            }
        }
    }

    const uint32_t aHi = a_lane_base(smb + E_AHI, wm, lane);
    const uint32_t aLo = a_lane_base(smb + E_ALO, wm, lane);
    const uint32_t bHi = b_lane_base(smb + E_BHI, wn, lane);
    const uint32_t bLo = b_lane_base(smb + E_BLO, wn, lane);
    float* stg = (float*)(sm + E_BHI);

    float d[4][4][4];
    #pragma unroll
    for (int f = 0; f < 4; f++)
        #pragma unroll
        for (int g = 0; g < 4; g++)
            #pragma unroll
            for (int c = 0; c < 4; c++) d[f][g][c] = 0.f;

    #pragma unroll 1
    for (int kc = 0; kc < 2; kc++) {
        cp_wait0();
        __syncthreads();
        mma_chunk(d, aHi + kc * 256, aLo + kc * 256, bHi, bLo);
        __syncthreads();
        if (kc == 0)
            load_B_async(smb + E_BHI, smb + E_BLO,
                         g_eBhi4 + CHUNK_U4, g_eBlo4 + CHUNK_U4, tid);
    }

    // --- staged, coalesced epilogue with fused b2 ---
    stage_acc(stg, d, wm, wn, lane);
    __syncthreads();
    {
        const int c = (tid & 31) * 4;
        float4 bb = *(const float4*)(b2 + c);
        #pragma unroll
        for (int i = 0; i < 16; i++) {
            int idx = i * 256 + tid;
            int row = idx >> 5;
            int e = ebase + row;
            if (e < E_EDGES) {
                float4 v = *(const float4*)(stg + row * STG_PITCH + c);
                *(float4*)(out + (size_t)e * 128 + c) =
                    make_float4(v.x + bb.x, v.y + bb.y, v.z + bb.z, v.w + bb.w);
            }
        }
    }
}

// ---------------------------------------------------------------------------
// launch — inputs resolved by unique element counts
// ---------------------------------------------------------------------------
extern "C" void kernel_launch(void* const* d_in, const int* in_sizes, int n_in,
                              void* d_out, int out_size) {
    const float* z = nullptr;
    const void* ei = nullptr;
    const float* W1 = nullptr;
    const float* b1 = nullptr;
    const float* W2 = nullptr;
    const float* b2 = nullptr;
    for (int i = 0; i < n_in; i++) {
        switch (in_sizes[i]) {
            case 25600000: z = (const float*)d_in[i]; break;
            case 1000000:  ei = d_in[i];              break;
            case 131072:   W1 = (const float*)d_in[i]; break;
            case 256:      b1 = (const float*)d_in[i]; break;
            case 32768:    W2 = (const float*)d_in[i]; break;
            case 128:      b2 = (const float*)d_in[i]; break;
            default: break;
        }
    }
    float* out = (float*)d_out;

    cudaFuncSetAttribute(node_mma, cudaFuncAttributeMaxDynamicSharedMemorySize, SM_BYTES);
    cudaFuncSetAttribute(edge_mma, cudaFuncAttributeMaxDynamicSharedMemorySize, SM_E);

    detect_kernel<<<1, 32>>>((const unsigned*)ei);
    prep_kernel<<<640, 256>>>(W1, W2);
    node_mma<<<(N_NODES + 127) / 128, 256, SM_BYTES>>>(z);
    edge_mma<<<(E_EDGES + 127) / 128, 256, SM_E>>>(ei, b1, b2, out);
}

// round 14
// speedup vs baseline: 1.3912x; 1.0004x over previous
#include <cuda_runtime.h>
#include <cuda_bf16.h>
#include <cstdint>

#define N_NODES 100000
#define E_EDGES 500000

// ---------------------------------------------------------------------------
// Device scratch
// ---------------------------------------------------------------------------
__device__ uint4 g_UVq4[(size_t)N_NODES * 64];  // int16 UV rows: [node][512]
__device__ float g_sc[N_NODES * 16];            // per (node, 32-col chunk) scale
__device__ uint4 g_nBhi4[16384];                // node B: 8 chunks x 128x128 bf16
__device__ uint4 g_nBlo4[16384];
__device__ uint4 g_eBhi4[4096];                 // edge B (W2): 2 chunks
__device__ uint4 g_eBlo4[4096];
__device__ int   g_idx64;

#define CHUNK_U4 2048   // 128x128 bf16 = 2048 uint4 (16 uint4 per 128-row)

#define PITCH_A  528    // A row: 256 bf16 + pad
#define EP       144    // B quarter row: 64 bf16 (128B) + 16 pad
#define QB       (128 * EP)   // 18432

// ---------------- node smem layout ----------------
#define N_AHI  0
#define N_ALO  67584
#define N_B0H  (2 * 67584)           // 135168
#define SM_N   (N_B0H + 4 * QB)      // 208896

// ---------------- edge smem layout ----------------
#define E_SRC  0
#define E_DST  512
#define E_AHI  1536
#define E_ALO  (1536 + 67584)
#define E_B0H  (1536 + 2 * 67584)    // 136704
#define SM_E   (E_B0H + 4 * QB)      // 210432
#define STG_PITCH 132

__device__ __forceinline__ uint32_t smem_u32(const void* p) {
    uint32_t a;
    asm("{ .reg .u64 t; cvta.to.shared.u64 t, %1; cvt.u32.u64 %0, t; }" : "=r"(a) : "l"(p));
    return a;
}

__device__ __forceinline__ void ldsm_x4(uint32_t* r, uint32_t addr) {
    asm volatile("ldmatrix.sync.aligned.m8n8.x4.shared.b16 {%0,%1,%2,%3}, [%4];"
                 : "=r"(r[0]), "=r"(r[1]), "=r"(r[2]), "=r"(r[3]) : "r"(addr));
}

__device__ __forceinline__ void mma16816(float* d, const uint32_t* a, const uint32_t* b) {
    asm volatile(
        "mma.sync.aligned.m16n8k16.row.col.f32.bf16.bf16.f32 "
        "{%0,%1,%2,%3},{%4,%5,%6,%7},{%8,%9},{%0,%1,%2,%3};"
        : "+f"(d[0]), "+f"(d[1]), "+f"(d[2]), "+f"(d[3])
        : "r"(a[0]), "r"(a[1]), "r"(a[2]), "r"(a[3]), "r"(b[0]), "r"(b[1]));
}

__device__ __forceinline__ void cpasync16(uint32_t saddr, const void* g) {
    asm volatile("cp.async.ca.shared.global [%0], [%1], 16;" :: "r"(saddr), "l"(g));
}
__device__ __forceinline__ void cp_commit() { asm volatile("cp.async.commit_group;"); }
__device__ __forceinline__ void cp_wait0()  { asm volatile("cp.async.wait_group 0;" ::: "memory"); }
__device__ __forceinline__ void cp_wait1()  { asm volatile("cp.async.wait_group 1;" ::: "memory"); }

// packed bf16 split
__device__ __forceinline__ void split2(float a, float b, uint32_t& hi, uint32_t& lo) {
    uint32_t h;
    asm("cvt.rn.bf16x2.f32 %0, %1, %2;" : "=r"(h) : "f"(b), "f"(a));
    float ah = __uint_as_float(h << 16);
    float bh = __uint_as_float(h & 0xFFFF0000u);
    uint32_t l;
    asm("cvt.rn.bf16x2.f32 %0, %1, %2;" : "=r"(l) : "f"(b - bh), "f"(a - ah));
    hi = h;
    lo = l;
}

__device__ __forceinline__ void dq8(uint4 p, float s, float* f) {
    f[0] = (float)((short)(p.x & 0xFFFF)) * s; f[1] = (float)(((int)p.x) >> 16) * s;
    f[2] = (float)((short)(p.y & 0xFFFF)) * s; f[3] = (float)(((int)p.y) >> 16) * s;
    f[4] = (float)((short)(p.z & 0xFFFF)) * s; f[5] = (float)(((int)p.z) >> 16) * s;
    f[6] = (float)((short)(p.w & 0xFFFF)) * s; f[7] = (float)(((int)p.w) >> 16) * s;
}

__device__ __forceinline__ uint32_t pk16(float a, float b) {
    int ia = __float2int_rn(a), ib = __float2int_rn(b);
    return (uint32_t)(ia & 0xFFFF) | ((uint32_t)ib << 16);
}

// ---------------------------------------------------------------------------
// detect edge_index dtype (int64 vs int32)
// ---------------------------------------------------------------------------
__global__ void detect_kernel(const unsigned* __restrict__ ei) {
    if (threadIdx.x == 0 && blockIdx.x == 0) {
        int ok = 1;
        #pragma unroll 1
        for (int i = 0; i < 256; i++)
            if (ei[2 * i + 1] != 0u) { ok = 0; break; }
        g_idx64 = ok;
    }
}

// ---------------------------------------------------------------------------
// prep: split weights into bf16 hi/lo chunk blobs [chunk][row][k] (128x128)
// ---------------------------------------------------------------------------
__global__ void prep_kernel(const float* __restrict__ W1, const float* __restrict__ W2) {
    int idx = blockIdx.x * blockDim.x + threadIdx.x;
    float v;
    uint32_t off;
    __nv_bfloat16 *dh, *dl;
    if (idx < 131072) {
        int j = idx >> 8, k = idx & 255;
        v = (j < 256) ? W1[j * 512 + k] : W1[(j - 256) * 512 + 256 + k];
        int nc = j >> 7, row = j & 127, kc = k >> 7, kp = k & 127;
        off = (uint32_t)(kc * 4 + nc) * 16384u + row * 128 + kp;
        dh = (__nv_bfloat16*)g_nBhi4; dl = (__nv_bfloat16*)g_nBlo4;
    } else {
        int e = idx - 131072;
        if (e >= 32768) return;
        int n = e >> 8, k = e & 255;
        v = W2[n * 256 + k];
        int kc = k >> 7, kp = k & 127;
        off = (uint32_t)kc * 16384u + n * 128 + kp;
        dh = (__nv_bfloat16*)g_eBhi4; dl = (__nv_bfloat16*)g_eBlo4;
    }
    __nv_bfloat16 h = __float2bfloat16_rn(v);
    dh[off] = h;
    dl[off] = __float2bfloat16_rn(v - __bfloat162float(h));
}

// ---------------------------------------------------------------------------
// shared helpers
// ---------------------------------------------------------------------------
// async load one 64-k B quarter (hi+lo): 128 rows x 8 uint4 each
__device__ __forceinline__ void load_Bq(uint32_t dstH, uint32_t dstL,
                                        const uint4* blobH, const uint4* blobL,
                                        int h, int tid) {
    #pragma unroll
    for (int i = 0; i < 4; i++) {
        int idx = i * 256 + tid;          // 0..1023
        int n = idx >> 3, j = idx & 7;
        uint32_t d = n * EP + j * 16;
        cpasync16(dstH + d, blobH + n * 16 + h * 8 + j);
        cpasync16(dstL + d, blobL + n * 16 + h * 8 + j);
    }
    cp_commit();
}

// 4 k-steps (64 k) of 3-pass bf16 mma
__device__ __forceinline__ void mma_q(float d[4][4][4],
                                      uint32_t aHi, uint32_t aLo,
                                      uint32_t bHi, uint32_t bLo) {
    #pragma unroll
    for (int ks = 0; ks < 4; ks++) {
        uint32_t Ah[4][4], Al[4][4], Bh[2][4], Bl[2][4];
        #pragma unroll
        for (int f = 0; f < 4; f++) {
            ldsm_x4(Ah[f], aHi + f * (16 * PITCH_A) + ks * 32);
            ldsm_x4(Al[f], aLo + f * (16 * PITCH_A) + ks * 32);
        }
        #pragma unroll
        for (int gp = 0; gp < 2; gp++) {
            ldsm_x4(Bh[gp], bHi + gp * (16 * EP) + ks * 32);
            ldsm_x4(Bl[gp], bLo + gp * (16 * EP) + ks * 32);
        }
        #pragma unroll
        for (int f = 0; f < 4; f++)
            #pragma unroll
            for (int g = 0; g < 4; g++) {
                const uint32_t* bh = &Bh[g >> 1][(g & 1) * 2];
                const uint32_t* bl = &Bl[g >> 1][(g & 1) * 2];
                mma16816(d[f][g], Ah[f], bh);
                mma16816(d[f][g], Ah[f], bl);
                mma16816(d[f][g], Al[f], bh);
            }
    }
}

__device__ __forceinline__ uint32_t a_lane_base(uint32_t smA, int wm, int lane) {
    int row = wm * 64 + (lane & 7) + ((lane >> 3) & 1) * 8;
    return smA + row * PITCH_A + ((lane >> 4) & 1) * 16;
}
__device__ __forceinline__ uint32_t b_lane_off(int wn, int lane) {
    int n = wn * 32 + (lane & 7) + ((lane >> 4) & 1) * 8;
    return (uint32_t)(n * EP + ((lane >> 3) & 1) * 16);
}

// ---------------------------------------------------------------------------
// node kernel: UV tile -> int16 quantized, per-(node, 32col) scales
// B streamed in double-buffered 64-k quarters (16 quarters total)
// ---------------------------------------------------------------------------
__global__ void __launch_bounds__(256, 1) node_mma(const float* __restrict__ Z) {
    extern __shared__ char sm[];
    const uint32_t smb = smem_u32(sm);
    const int tid = threadIdx.x, lane = tid & 31, wid = tid >> 5;
    const int wm = wid & 1, wn = wid >> 1;
    const int mbase = blockIdx.x * 128;

    // prefetch quarter 0 (chunk 0, h=0)
    load_Bq(smb + N_B0H, smb + N_B0H + QB, g_nBhi4, g_nBlo4, 0, tid);

    // --- stage A: full K=256, split to bf16 hi/lo ---
    {
        const int lrow = tid >> 3;
        const int lk = (tid & 7) * 4;
        #pragma unroll 1
        for (int s = 0; s < 4; s++) {
            int row = s * 32 + lrow;
            int gr = min(mbase + row, N_NODES - 1);
            const float* zr = Z + (size_t)gr * 256;
            char* ah = sm + N_AHI + row * PITCH_A;
            char* al = sm + N_ALO + row * PITCH_A;
            #pragma unroll
            for (int i = 0; i < 8; i++) {
                int k = lk + i * 32;
                float4 z4 = *(const float4*)(zr + k);
                uint32_t h0, l0, h1, l1;
                split2(z4.x, z4.y, h0, l0);
                split2(z4.z, z4.w, h1, l1);
                *(uint2*)(ah + k * 2) = make_uint2(h0, h1);
                *(uint2*)(al + k * 2) = make_uint2(l0, l1);
            }
        }
    }

    const uint32_t aHi = a_lane_base(smb + N_AHI, wm, lane);
    const uint32_t aLo = a_lane_base(smb + N_ALO, wm, lane);
    const uint32_t bOff = b_lane_off(wn, lane);
    const uint32_t bufH[2] = {smb + N_B0H, smb + N_B0H + 2 * QB};

    float d[4][4][4];
    #pragma unroll
    for (int f = 0; f < 4; f++)
        #pragma unroll
        for (int g = 0; g < 4; g++)
            #pragma unroll
            for (int c = 0; c < 4; c++) d[f][g][c] = 0.f;

    #pragma unroll 1
    for (int t = 0; t < 16; t++) {
        if (t < 15) {
            int tn = t + 1;
            int nc2 = tn >> 2, qk2 = tn & 3;
            int ch = (qk2 >> 1) * 4 + nc2;
            load_Bq(bufH[tn & 1], bufH[tn & 1] + QB,
                    g_nBhi4 + ch * CHUNK_U4, g_nBlo4 + ch * CHUNK_U4, qk2 & 1, tid);
            cp_wait1();
        } else {
            cp_wait0();
        }
        __syncthreads();
        const int qk = t & 3;
        mma_q(d, aHi + qk * 128, aLo + qk * 128,
              bufH[t & 1] + bOff, bufH[t & 1] + QB + bOff);

        if (qk == 3) {
            // --- register epilogue: per-(row, 32col) quantize ---
            const int nc = t >> 2;
            #pragma unroll
            for (int f = 0; f < 4; f++) {
                float m0 = 0.f, m1 = 0.f;
                #pragma unroll
                for (int g = 0; g < 4; g++) {
                    m0 = fmaxf(m0, fmaxf(fabsf(d[f][g][0]), fabsf(d[f][g][1])));
                    m1 = fmaxf(m1, fmaxf(fabsf(d[f][g][2]), fabsf(d[f][g][3])));
                }
                m0 = fmaxf(m0, __shfl_xor_sync(0xFFFFFFFFu, m0, 1));
                m0 = fmaxf(m0, __shfl_xor_sync(0xFFFFFFFFu, m0, 2));
                m1 = fmaxf(m1, __shfl_xor_sync(0xFFFFFFFFu, m1, 1));
                m1 = fmaxf(m1, __shfl_xor_sync(0xFFFFFFFFu, m1, 2));
                float s0 = (m0 > 1e-30f) ? m0 * (1.f / 32704.f) : 1.f;
                float s1 = (m1 > 1e-30f) ? m1 * (1.f / 32704.f) : 1.f;
                float i0 = 1.f / s0, i1 = 1.f / s1;
                int r0 = mbase + wm * 64 + f * 16 + (lane >> 2);
                int r1 = r0 + 8;
                if ((lane & 3) == 0) {
                    if (r0 < N_NODES) g_sc[r0 * 16 + nc * 4 + wn] = s0;
                    if (r1 < N_NODES) g_sc[r1 * 16 + nc * 4 + wn] = s1;
                }
                uint32_t* q0 = (uint32_t*)g_UVq4 + (size_t)min(r0, N_NODES - 1) * 256
                             + nc * 64 + wn * 16 + (lane & 3);
                uint32_t* q1 = (uint32_t*)g_UVq4 + (size_t)min(r1, N_NODES - 1) * 256
                             + nc * 64 + wn * 16 + (lane & 3);
                #pragma unroll
                for (int g = 0; g < 4; g++) {
                    if (r0 < N_NODES) q0[g * 4] = pk16(d[f][g][0] * i0, d[f][g][1] * i0);
                    if (r1 < N_NODES) q1[g * 4] = pk16(d[f][g][2] * i1, d[f][g][3] * i1);
                    d[f][g][0] = d[f][g][1] = d[f][g][2] = d[f][g][3] = 0.f;
                }
            }
        }
        __syncthreads();
    }
}

// ---------------------------------------------------------------------------
// edge kernel: gathers int16 UV (+32col scales), B in double-buffered quarters
// ---------------------------------------------------------------------------
__global__ void __launch_bounds__(256, 1) edge_mma(const void* __restrict__ EI,
                                                   const float* __restrict__ b1,
                                                   const float* __restrict__ b2,
                                                   float* __restrict__ out) {
    extern __shared__ char sm[];
    const uint32_t smb = smem_u32(sm);
    int* ssrc = (int*)(sm + E_SRC);
    int* sdst = (int*)(sm + E_DST);
    const int tid = threadIdx.x, lane = tid & 31, wid = tid >> 5;
    const int wm = wid & 1, wn = wid >> 1;
    const int ebase = blockIdx.x * 128;

    // prefetch B quarter 0
    load_Bq(smb + E_B0H, smb + E_B0H + QB, g_eBhi4, g_eBlo4, 0, tid);

    if (tid < 128) {
        int e = ebase + tid;
        long long s = 0, dd = 0;
        if (e < E_EDGES) {
            if (g_idx64) {
                const long long* p = (const long long*)EI;
                s = p[e]; dd = p[e + E_EDGES];
            } else {
                const int* p = (const int*)EI;
                s = p[e]; dd = p[e + E_EDGES];
            }
        }
        ssrc[tid] = min(max((int)s, 0), N_NODES - 1);
        sdst[tid] = min(max((int)dd, 0), N_NODES - 1);
    }
    __syncthreads();

    // --- stage A: gather int16 U/V, dequant (32-col scales), +b1, relu, split ---
    {
        const int lrow = tid >> 3;
        const int j = tid & 7;
        const int jj = j >> 2;
        #pragma unroll 1
        for (int s = 0; s < 4; s++) {
            int row = s * 32 + lrow;
            int src = ssrc[row], dst = sdst[row];
            const uint4* Uq = g_UVq4 + (size_t)src * 64;
            const uint4* Vq = g_UVq4 + (size_t)dst * 64 + 32;
            const float* scU = g_sc + src * 16;
            const float* scV = g_sc + dst * 16 + 8;
            char* ah = sm + E_AHI + row * PITCH_A;
            char* al = sm + E_ALO + row * PITCH_A;
            #pragma unroll
            for (int i = 0; i < 4; i++) {
                int k = j * 8 + i * 64;
                uint4 up = Uq[j + i * 8];
                uint4 vp = Vq[j + i * 8];
                float su = scU[i * 2 + jj];
                float sv = scV[i * 2 + jj];
                float uu[8], vv[8];
                dq8(up, su, uu);
                dq8(vp, sv, vv);
                float4 c0 = *(const float4*)(b1 + k);
                float4 c1 = *(const float4*)(b1 + k + 4);
                float h0 = fmaxf(uu[0] + vv[0] + c0.x, 0.f);
                float h1 = fmaxf(uu[1] + vv[1] + c0.y, 0.f);
                float h2 = fmaxf(uu[2] + vv[2] + c0.z, 0.f);
                float h3 = fmaxf(uu[3] + vv[3] + c0.w, 0.f);
                float h4 = fmaxf(uu[4] + vv[4] + c1.x, 0.f);
                float h5 = fmaxf(uu[5] + vv[5] + c1.y, 0.f);
                float h6 = fmaxf(uu[6] + vv[6] + c1.z, 0.f);
                float h7 = fmaxf(uu[7] + vv[7] + c1.w, 0.f);
                uint4 hi, lo;
                split2(h0, h1, hi.x, lo.x);
                split2(h2, h3, hi.y, lo.y);
                split2(h4, h5, hi.z, lo.z);
                split2(h6, h7, hi.w, lo.w);
                *(uint4*)(ah + k * 2) = hi;
                *(uint4*)(al + k * 2) = lo;
            }
        }
    }

    const uint32_t aHi = a_lane_base(smb + E_AHI, wm, lane);
    const uint32_t aLo = a_lane_base(smb + E_ALO, wm, lane);
    const uint32_t bOff = b_lane_off(wn, lane);
    const uint32_t bufH[2] = {smb + E_B0H, smb + E_B0H + 2 * QB};

    float d[4][4][4];
    #pragma unroll
    for (int f = 0; f < 4; f++)
        #pragma unroll
        for (int g = 0; g < 4; g++)
            #pragma unroll
            for (int c = 0; c < 4; c++) d[f][g][c] = 0.f;

    #pragma unroll 1
    for (int t = 0; t < 4; t++) {
        if (t < 3) {
            int tn = t + 1;
            load_Bq(bufH[tn & 1], bufH[tn & 1] + QB,
                    g_eBhi4 + (tn >> 1) * CHUNK_U4, g_eBlo4 + (tn >> 1) * CHUNK_U4,
                    tn & 1, tid);
            cp_wait1();
        } else {
            cp_wait0();
        }
        __syncthreads();
        mma_q(d, aHi + t * 128, aLo + t * 128,
              bufH[t & 1] + bOff, bufH[t & 1] + QB + bOff);
        __syncthreads();
    }

    // --- staged, coalesced epilogue with fused b2 (B area is dead) ---
    float* stg = (float*)(sm + E_B0H);
    #pragma unroll
    for (int g = 0; g < 4; g++) {
        int col = wn * 32 + g * 8 + (lane & 3) * 2;
        #pragma unroll
        for (int f = 0; f < 4; f++) {
            int r0 = wm * 64 + f * 16 + (lane >> 2);
            *(float2*)(stg + r0 * STG_PITCH + col) = make_float2(d[f][g][0], d[f][g][1]);
            *(float2*)(stg + (r0 + 8) * STG_PITCH + col) = make_float2(d[f][g][2], d[f][g][3]);
        }
    }
    __syncthreads();
    {
        const int c = (tid & 31) * 4;
        float4 bb = *(const float4*)(b2 + c);
        #pragma unroll
        for (int i = 0; i < 16; i++) {
            int idx = i * 256 + tid;
            int row = idx >> 5;
            int e = ebase + row;
            if (e < E_EDGES) {
                float4 v = *(const float4*)(stg + row * STG_PITCH + c);
                *(float4*)(out + (size_t)e * 128 + c) =
                    make_float4(v.x + bb.x, v.y + bb.y, v.z + bb.z, v.w + bb.w);
            }
        }
    }
}

// ---------------------------------------------------------------------------
// launch — inputs resolved by unique element counts
// ---------------------------------------------------------------------------
extern "C" void kernel_launch(void* const* d_in, const int* in_sizes, int n_in,
                              void* d_out, int out_size) {
    const float* z = nullptr;
    const void* ei = nullptr;
    const float* W1 = nullptr;
    const float* b1 = nullptr;
    const float* W2 = nullptr;
    const float* b2 = nullptr;
    for (int i = 0; i < n_in; i++) {
        switch (in_sizes[i]) {
            case 25600000: z = (const float*)d_in[i]; break;
            case 1000000:  ei = d_in[i];              break;
            case 131072:   W1 = (const float*)d_in[i]; break;
            case 256:      b1 = (const float*)d_in[i]; break;
            case 32768:    W2 = (const float*)d_in[i]; break;
            case 128:      b2 = (const float*)d_in[i]; break;
            default: break;
        }
    }
    float* out = (float*)d_out;

    cudaFuncSetAttribute(node_mma, cudaFuncAttributeMaxDynamicSharedMemorySize, SM_N);
    cudaFuncSetAttribute(edge_mma, cudaFuncAttributeMaxDynamicSharedMemorySize, SM_E);

    detect_kernel<<<1, 32>>>((const unsigned*)ei);
    prep_kernel<<<640, 256>>>(W1, W2);
    node_mma<<<(N_NODES + 127) / 128, 256, SM_N>>>(z);
    edge_mma<<<(E_EDGES + 127) / 128, 256, SM_E>>>(ei, b1, b2, out);
}

// round 15
// speedup vs baseline: 1.4048x; 1.0098x over previous
#include <cuda_runtime.h>
#include <cuda_bf16.h>
#include <cstdint>

#define N_NODES 100000
#define E_EDGES 500000

// ---------------------------------------------------------------------------
// Device scratch
// ---------------------------------------------------------------------------
__device__ uint4 g_UVq4[(size_t)N_NODES * 64];  // int16 UV rows: [node][512] (b1 folded into U)
__device__ float g_sc[N_NODES * 16];            // per (node, 32-col chunk) scale
__device__ uint4 g_nBhi4[16384];                // node B: 8 chunks x 128x128 bf16
__device__ uint4 g_nBlo4[16384];
__device__ uint4 g_eBhi4[4096];                 // edge B (W2): 2 chunks
__device__ uint4 g_eBlo4[4096];
__device__ int   g_idx64;

#define CHUNK_U4 2048   // 128x128 bf16 = 2048 uint4 (16 uint4 per 128-row)

#define PITCH_A  528    // A row: 256 bf16 + pad
#define EP       144    // B quarter row: 64 bf16 (128B) + 16 pad
#define QB       (128 * EP)   // 18432
#define SPITCH   68     // staging pitch in uint32 (64 + 4 pad)

// ---------------- node smem layout ----------------
#define N_AHI  0
#define N_ALO  67584
#define N_B0H  (2 * 67584)           // 135168
#define SM_N   (N_B0H + 4 * QB)      // 208896

// ---------------- edge smem layout ----------------
#define E_SRC  0
#define E_DST  512
#define E_AHI  1536
#define E_ALO  (1536 + 67584)
#define E_B0H  (1536 + 2 * 67584)    // 136704
#define SM_E   (E_B0H + 4 * QB)      // 210432
#define STG_PITCH 132

__device__ __forceinline__ uint32_t smem_u32(const void* p) {
    uint32_t a;
    asm("{ .reg .u64 t; cvta.to.shared.u64 t, %1; cvt.u32.u64 %0, t; }" : "=r"(a) : "l"(p));
    return a;
}

__device__ __forceinline__ void ldsm_x4(uint32_t* r, uint32_t addr) {
    asm volatile("ldmatrix.sync.aligned.m8n8.x4.shared.b16 {%0,%1,%2,%3}, [%4];"
                 : "=r"(r[0]), "=r"(r[1]), "=r"(r[2]), "=r"(r[3]) : "r"(addr));
}

__device__ __forceinline__ void mma16816(float* d, const uint32_t* a, const uint32_t* b) {
    asm volatile(
        "mma.sync.aligned.m16n8k16.row.col.f32.bf16.bf16.f32 "
        "{%0,%1,%2,%3},{%4,%5,%6,%7},{%8,%9},{%0,%1,%2,%3};"
        : "+f"(d[0]), "+f"(d[1]), "+f"(d[2]), "+f"(d[3])
        : "r"(a[0]), "r"(a[1]), "r"(a[2]), "r"(a[3]), "r"(b[0]), "r"(b[1]));
}

__device__ __forceinline__ void cpasync16(uint32_t saddr, const void* g) {
    asm volatile("cp.async.ca.shared.global [%0], [%1], 16;" :: "r"(saddr), "l"(g));
}
__device__ __forceinline__ void cp_commit() { asm volatile("cp.async.commit_group;"); }
__device__ __forceinline__ void cp_wait0()  { asm volatile("cp.async.wait_group 0;" ::: "memory"); }
__device__ __forceinline__ void cp_wait1()  { asm volatile("cp.async.wait_group 1;" ::: "memory"); }

// packed bf16 split
__device__ __forceinline__ void split2(float a, float b, uint32_t& hi, uint32_t& lo) {
    uint32_t h;
    asm("cvt.rn.bf16x2.f32 %0, %1, %2;" : "=r"(h) : "f"(b), "f"(a));
    float ah = __uint_as_float(h << 16);
    float bh = __uint_as_float(h & 0xFFFF0000u);
    uint32_t l;
    asm("cvt.rn.bf16x2.f32 %0, %1, %2;" : "=r"(l) : "f"(b - bh), "f"(a - ah));
    hi = h;
    lo = l;
}

__device__ __forceinline__ void dq8(uint4 p, float s, float* f) {
    f[0] = (float)((short)(p.x & 0xFFFF)) * s; f[1] = (float)(((int)p.x) >> 16) * s;
    f[2] = (float)((short)(p.y & 0xFFFF)) * s; f[3] = (float)(((int)p.y) >> 16) * s;
    f[4] = (float)((short)(p.z & 0xFFFF)) * s; f[5] = (float)(((int)p.z) >> 16) * s;
    f[6] = (float)((short)(p.w & 0xFFFF)) * s; f[7] = (float)(((int)p.w) >> 16) * s;
}

__device__ __forceinline__ uint32_t pk16(float a, float b) {
    int ia = __float2int_rn(a), ib = __float2int_rn(b);
    return (uint32_t)(ia & 0xFFFF) | ((uint32_t)ib << 16);
}

// ---------------------------------------------------------------------------
// detect edge_index dtype (int64 vs int32)
// ---------------------------------------------------------------------------
__global__ void detect_kernel(const unsigned* __restrict__ ei) {
    if (threadIdx.x == 0 && blockIdx.x == 0) {
        int ok = 1;
        #pragma unroll 1
        for (int i = 0; i < 256; i++)
            if (ei[2 * i + 1] != 0u) { ok = 0; break; }
        g_idx64 = ok;
    }
}

// ---------------------------------------------------------------------------
// prep: split weights into bf16 hi/lo chunk blobs [chunk][row][k] (128x128)
// ---------------------------------------------------------------------------
__global__ void prep_kernel(const float* __restrict__ W1, const float* __restrict__ W2) {
    int idx = blockIdx.x * blockDim.x + threadIdx.x;
    float v;
    uint32_t off;
    __nv_bfloat16 *dh, *dl;
    if (idx < 131072) {
        int j = idx >> 8, k = idx & 255;
        v = (j < 256) ? W1[j * 512 + k] : W1[(j - 256) * 512 + 256 + k];
        int nc = j >> 7, row = j & 127, kc = k >> 7, kp = k & 127;
        off = (uint32_t)(kc * 4 + nc) * 16384u + row * 128 + kp;
        dh = (__nv_bfloat16*)g_nBhi4; dl = (__nv_bfloat16*)g_nBlo4;
    } else {
        int e = idx - 131072;
        if (e >= 32768) return;
        int n = e >> 8, k = e & 255;
        v = W2[n * 256 + k];
        int kc = k >> 7, kp = k & 127;
        off = (uint32_t)kc * 16384u + n * 128 + kp;
        dh = (__nv_bfloat16*)g_eBhi4; dl = (__nv_bfloat16*)g_eBlo4;
    }
    __nv_bfloat16 h = __float2bfloat16_rn(v);
    dh[off] = h;
    dl[off] = __float2bfloat16_rn(v - __bfloat162float(h));
}

// ---------------------------------------------------------------------------
// shared helpers
// ---------------------------------------------------------------------------
// async load one 64-k B quarter (hi+lo): 128 rows x 8 uint4 each
__device__ __forceinline__ void load_Bq(uint32_t dstH, uint32_t dstL,
                                        const uint4* blobH, const uint4* blobL,
                                        int h, int tid) {
    #pragma unroll
    for (int i = 0; i < 4; i++) {
        int idx = i * 256 + tid;          // 0..1023
        int n = idx >> 3, j = idx & 7;
        uint32_t d = n * EP + j * 16;
        cpasync16(dstH + d, blobH + n * 16 + h * 8 + j);
        cpasync16(dstL + d, blobL + n * 16 + h * 8 + j);
    }
    cp_commit();
}

// 4 k-steps (64 k) of 3-pass bf16 mma
__device__ __forceinline__ void mma_q(float d[4][4][4],
                                      uint32_t aHi, uint32_t aLo,
                                      uint32_t bHi, uint32_t bLo) {
    #pragma unroll
    for (int ks = 0; ks < 4; ks++) {
        uint32_t Ah[4][4], Al[4][4], Bh[2][4], Bl[2][4];
        #pragma unroll
        for (int f = 0; f < 4; f++) {
            ldsm_x4(Ah[f], aHi + f * (16 * PITCH_A) + ks * 32);
            ldsm_x4(Al[f], aLo + f * (16 * PITCH_A) + ks * 32);
        }
        #pragma unroll
        for (int gp = 0; gp < 2; gp++) {
            ldsm_x4(Bh[gp], bHi + gp * (16 * EP) + ks * 32);
            ldsm_x4(Bl[gp], bLo + gp * (16 * EP) + ks * 32);
        }
        #pragma unroll
        for (int f = 0; f < 4; f++)
            #pragma unroll
            for (int g = 0; g < 4; g++) {
                const uint32_t* bh = &Bh[g >> 1][(g & 1) * 2];
                const uint32_t* bl = &Bl[g >> 1][(g & 1) * 2];
                mma16816(d[f][g], Ah[f], bh);
                mma16816(d[f][g], Ah[f], bl);
                mma16816(d[f][g], Al[f], bh);
            }
    }
}

__device__ __forceinline__ uint32_t a_lane_base(uint32_t smA, int wm, int lane) {
    int row = wm * 64 + (lane & 7) + ((lane >> 3) & 1) * 8;
    return smA + row * PITCH_A + ((lane >> 4) & 1) * 16;
}
__device__ __forceinline__ uint32_t b_lane_off(int wn, int lane) {
    int n = wn * 32 + (lane & 7) + ((lane >> 4) & 1) * 8;
    return (uint32_t)(n * EP + ((lane >> 3) & 1) * 16);
}

// ---------------------------------------------------------------------------
// node kernel: UV tile (b1 folded into U) -> int16, coalesced staged epilogue
// ---------------------------------------------------------------------------
__global__ void __launch_bounds__(256, 1) node_mma(const float* __restrict__ Z,
                                                   const float* __restrict__ b1) {
    extern __shared__ char sm[];
    const uint32_t smb = smem_u32(sm);
    const int tid = threadIdx.x, lane = tid & 31, wid = tid >> 5;
    const int wm = wid & 1, wn = wid >> 1;
    const int mbase = blockIdx.x * 128;

    // prefetch quarter 0 (chunk 0, h=0)
    load_Bq(smb + N_B0H, smb + N_B0H + QB, g_nBhi4, g_nBlo4, 0, tid);

    // --- stage A: full K=256, split to bf16 hi/lo ---
    {
        const int lrow = tid >> 3;
        const int lk = (tid & 7) * 4;
        #pragma unroll 1
        for (int s = 0; s < 4; s++) {
            int row = s * 32 + lrow;
            int gr = min(mbase + row, N_NODES - 1);
            const float* zr = Z + (size_t)gr * 256;
            char* ah = sm + N_AHI + row * PITCH_A;
            char* al = sm + N_ALO + row * PITCH_A;
            #pragma unroll
            for (int i = 0; i < 8; i++) {
                int k = lk + i * 32;
                float4 z4 = *(const float4*)(zr + k);
                uint32_t h0, l0, h1, l1;
                split2(z4.x, z4.y, h0, l0);
                split2(z4.z, z4.w, h1, l1);
                *(uint2*)(ah + k * 2) = make_uint2(h0, h1);
                *(uint2*)(al + k * 2) = make_uint2(l0, l1);
            }
        }
    }

    const uint32_t aHi = a_lane_base(smb + N_AHI, wm, lane);
    const uint32_t aLo = a_lane_base(smb + N_ALO, wm, lane);
    const uint32_t bOff = b_lane_off(wn, lane);
    const uint32_t bufH[2] = {smb + N_B0H, smb + N_B0H + 2 * QB};

    float d[4][4][4];
    #pragma unroll
    for (int f = 0; f < 4; f++)
        #pragma unroll
        for (int g = 0; g < 4; g++)
            #pragma unroll
            for (int c = 0; c < 4; c++) d[f][g][c] = 0.f;

    #pragma unroll 1
    for (int t = 0; t < 16; t++) {
        if (t < 15) {
            int tn = t + 1;
            int nc2 = tn >> 2, qk2 = tn & 3;
            int ch = (qk2 >> 1) * 4 + nc2;
            load_Bq(bufH[tn & 1], bufH[tn & 1] + QB,
                    g_nBhi4 + ch * CHUNK_U4, g_nBlo4 + ch * CHUNK_U4, qk2 & 1, tid);
            cp_wait1();
        } else {
            cp_wait0();
        }
        __syncthreads();
        const int qk = t & 3;
        mma_q(d, aHi + qk * 128, aLo + qk * 128,
              bufH[t & 1] + bOff, bufH[t & 1] + QB + bOff);

        if (qk == 3) {
            const int nc = t >> 2;
            // fold b1 into U chunks (cols 0..255)
            if (nc < 2) {
                #pragma unroll
                for (int g = 0; g < 4; g++) {
                    int col = nc * 128 + wn * 32 + g * 8 + (lane & 3) * 2;
                    float2 bb = *(const float2*)(b1 + col);
                    #pragma unroll
                    for (int f = 0; f < 4; f++) {
                        d[f][g][0] += bb.x; d[f][g][1] += bb.y;
                        d[f][g][2] += bb.x; d[f][g][3] += bb.y;
                    }
                }
            }
            // mma(t) consumers done before we reuse its B slot as staging
            __syncthreads();
            uint32_t* S = (uint32_t*)(sm + (N_B0H - 0) + (t & 1) * 2 * QB);
            #pragma unroll
            for (int f = 0; f < 4; f++) {
                float m0 = 0.f, m1 = 0.f;
                #pragma unroll
                for (int g = 0; g < 4; g++) {
                    m0 = fmaxf(m0, fmaxf(fabsf(d[f][g][0]), fabsf(d[f][g][1])));
                    m1 = fmaxf(m1, fmaxf(fabsf(d[f][g][2]), fabsf(d[f][g][3])));
                }
                m0 = fmaxf(m0, __shfl_xor_sync(0xFFFFFFFFu, m0, 1));
                m0 = fmaxf(m0, __shfl_xor_sync(0xFFFFFFFFu, m0, 2));
                m1 = fmaxf(m1, __shfl_xor_sync(0xFFFFFFFFu, m1, 1));
                m1 = fmaxf(m1, __shfl_xor_sync(0xFFFFFFFFu, m1, 2));
                float s0 = (m0 > 1e-30f) ? m0 * (1.f / 32704.f) : 1.f;
                float s1 = (m1 > 1e-30f) ? m1 * (1.f / 32704.f) : 1.f;
                float i0 = 1.f / s0, i1 = 1.f / s1;
                int r0 = wm * 64 + f * 16 + (lane >> 2);
                int r1 = r0 + 8;
                if ((lane & 3) == 0) {
                    if (mbase + r0 < N_NODES) g_sc[(mbase + r0) * 16 + nc * 4 + wn] = s0;
                    if (mbase + r1 < N_NODES) g_sc[(mbase + r1) * 16 + nc * 4 + wn] = s1;
                }
                #pragma unroll
                for (int g = 0; g < 4; g++) {
                    int cu = wn * 16 + g * 4 + (lane & 3);
                    S[r0 * SPITCH + cu] = pk16(d[f][g][0] * i0, d[f][g][1] * i0);
                    S[r1 * SPITCH + cu] = pk16(d[f][g][2] * i1, d[f][g][3] * i1);
                    d[f][g][0] = d[f][g][1] = d[f][g][2] = d[f][g][3] = 0.f;
                }
            }
            __syncthreads();
            // coalesced write: 128 rows x 16 uint4
            #pragma unroll
            for (int i = 0; i < 8; i++) {
                int idx = i * 256 + tid;
                int row = idx >> 4, c = idx & 15;
                int node = mbase + row;
                if (node < N_NODES) {
                    const uint32_t* sp = S + row * SPITCH + c * 4;
                    uint4 v = make_uint4(sp[0], sp[1], sp[2], sp[3]);
                    g_UVq4[(size_t)node * 64 + nc * 16 + c] = v;
                }
            }
        }
        __syncthreads();
    }
}

// ---------------------------------------------------------------------------
// edge kernel: gathers int16 UV (+32col scales), h = relu(U'+V) (b1 in U')
// ---------------------------------------------------------------------------
__global__ void __launch_bounds__(256, 1) edge_mma(const void* __restrict__ EI,
                                                   const float* __restrict__ b2,
                                                   float* __restrict__ out) {
    extern __shared__ char sm[];
    const uint32_t smb = smem_u32(sm);
    int* ssrc = (int*)(sm + E_SRC);
    int* sdst = (int*)(sm + E_DST);
    const int tid = threadIdx.x, lane = tid & 31, wid = tid >> 5;
    const int wm = wid & 1, wn = wid >> 1;
    const int ebase = blockIdx.x * 128;

    // prefetch B quarter 0
    load_Bq(smb + E_B0H, smb + E_B0H + QB, g_eBhi4, g_eBlo4, 0, tid);

    if (tid < 128) {
        int e = ebase + tid;
        long long s = 0, dd = 0;
        if (e < E_EDGES) {
            if (g_idx64) {
                const long long* p = (const long long*)EI;
                s = p[e]; dd = p[e + E_EDGES];
            } else {
                const int* p = (const int*)EI;
                s = p[e]; dd = p[e + E_EDGES];
            }
        }
        ssrc[tid] = min(max((int)s, 0), N_NODES - 1);
        sdst[tid] = min(max((int)dd, 0), N_NODES - 1);
    }
    __syncthreads();

    // --- stage A: gather int16 U'/V, dequant (32-col scales), relu, split ---
    {
        const int lrow = tid >> 3;
        const int j = tid & 7;
        const int jj = j >> 2;
        #pragma unroll 1
        for (int s = 0; s < 4; s++) {
            int row = s * 32 + lrow;
            int src = ssrc[row], dst = sdst[row];
            const uint4* Uq = g_UVq4 + (size_t)src * 64;
            const uint4* Vq = g_UVq4 + (size_t)dst * 64 + 32;
            const float* scU = g_sc + src * 16;
            const float* scV = g_sc + dst * 16 + 8;
            char* ah = sm + E_AHI + row * PITCH_A;
            char* al = sm + E_ALO + row * PITCH_A;
            #pragma unroll
            for (int i = 0; i < 4; i++) {
                int k = j * 8 + i * 64;
                uint4 up = Uq[j + i * 8];
                uint4 vp = Vq[j + i * 8];
                float su = scU[i * 2 + jj];
                float sv = scV[i * 2 + jj];
                float uu[8], vv[8];
                dq8(up, su, uu);
                dq8(vp, sv, vv);
                float h0 = fmaxf(uu[0] + vv[0], 0.f);
                float h1 = fmaxf(uu[1] + vv[1], 0.f);
                float h2 = fmaxf(uu[2] + vv[2], 0.f);
                float h3 = fmaxf(uu[3] + vv[3], 0.f);
                float h4 = fmaxf(uu[4] + vv[4], 0.f);
                float h5 = fmaxf(uu[5] + vv[5], 0.f);
                float h6 = fmaxf(uu[6] + vv[6], 0.f);
                float h7 = fmaxf(uu[7] + vv[7], 0.f);
                uint4 hi, lo;
                split2(h0, h1, hi.x, lo.x);
                split2(h2, h3, hi.y, lo.y);
                split2(h4, h5, hi.z, lo.z);
                split2(h6, h7, hi.w, lo.w);
                *(uint4*)(ah + k * 2) = hi;
                *(uint4*)(al + k * 2) = lo;
            }
        }
    }

    const uint32_t aHi = a_lane_base(smb + E_AHI, wm, lane);
    const uint32_t aLo = a_lane_base(smb + E_ALO, wm, lane);
    const uint32_t bOff = b_lane_off(wn, lane);
    const uint32_t bufH[2] = {smb + E_B0H, smb + E_B0H + 2 * QB};

    float d[4][4][4];
    #pragma unroll
    for (int f = 0; f < 4; f++)
        #pragma unroll
        for (int g = 0; g < 4; g++)
            #pragma unroll
            for (int c = 0; c < 4; c++) d[f][g][c] = 0.f;

    #pragma unroll 1
    for (int t = 0; t < 4; t++) {
        if (t < 3) {
            int tn = t + 1;
            load_Bq(bufH[tn & 1], bufH[tn & 1] + QB,
                    g_eBhi4 + (tn >> 1) * CHUNK_U4, g_eBlo4 + (tn >> 1) * CHUNK_U4,
                    tn & 1, tid);
            cp_wait1();
        } else {
            cp_wait0();
        }
        __syncthreads();
        mma_q(d, aHi + t * 128, aLo + t * 128,
              bufH[t & 1] + bOff, bufH[t & 1] + QB + bOff);
        __syncthreads();
    }

    // --- staged, coalesced epilogue with fused b2 (B area is dead) ---
    float* stg = (float*)(sm + E_B0H);
    #pragma unroll
    for (int g = 0; g < 4; g++) {
        int col = wn * 32 + g * 8 + (lane & 3) * 2;
        #pragma unroll
        for (int f = 0; f < 4; f++) {
            int r0 = wm * 64 + f * 16 + (lane >> 2);
            *(float2*)(stg + r0 * STG_PITCH + col) = make_float2(d[f][g][0], d[f][g][1]);
            *(float2*)(stg + (r0 + 8) * STG_PITCH + col) = make_float2(d[f][g][2], d[f][g][3]);
        }
    }
    __syncthreads();
    {
        const int c = (tid & 31) * 4;
        float4 bb = *(const float4*)(b2 + c);
        #pragma unroll
        for (int i = 0; i < 16; i++) {
            int idx = i * 256 + tid;
            int row = idx >> 5;
            int e = ebase + row;
            if (e < E_EDGES) {
                float4 v = *(const float4*)(stg + row * STG_PITCH + c);
                *(float4*)(out + (size_t)e * 128 + c) =
                    make_float4(v.x + bb.x, v.y + bb.y, v.z + bb.z, v.w + bb.w);
            }
        }
    }
}

// ---------------------------------------------------------------------------
// launch — inputs resolved by unique element counts
// ---------------------------------------------------------------------------
extern "C" void kernel_launch(void* const* d_in, const int* in_sizes, int n_in,
                              void* d_out, int out_size) {
    const float* z = nullptr;
    const void* ei = nullptr;
    const float* W1 = nullptr;
    const float* b1 = nullptr;
    const float* W2 = nullptr;
    const float* b2 = nullptr;
    for (int i = 0; i < n_in; i++) {
        switch (in_sizes[i]) {
            case 25600000: z = (const float*)d_in[i]; break;
            case 1000000:  ei = d_in[i];              break;
            case 131072:   W1 = (const float*)d_in[i]; break;
            case 256:      b1 = (const float*)d_in[i]; break;
            case 32768:    W2 = (const float*)d_in[i]; break;
            case 128:      b2 = (const float*)d_in[i]; break;
            default: break;
        }
    }
    float* out = (float*)d_out;

    cudaFuncSetAttribute(node_mma, cudaFuncAttributeMaxDynamicSharedMemorySize, SM_N);
    cudaFuncSetAttribute(edge_mma, cudaFuncAttributeMaxDynamicSharedMemorySize, SM_E);

    detect_kernel<<<1, 32>>>((const unsigned*)ei);
    prep_kernel<<<640, 256>>>(W1, W2);
    node_mma<<<(N_NODES + 127) / 128, 256, SM_N>>>(z, b1);
    edge_mma<<<(E_EDGES + 127) / 128, 256, SM_E>>>(ei, b2, out);
}